// round 1
// baseline (speedup 1.0000x reference)
#include <cuda_runtime.h>
#include <cuda_bf16.h>
#include <math.h>

// Problem constants (fixed by reference)
#define BATCH 2
#define SEQ 2048
#define D_IN 2048
#define D_OUT 2048
#define NUM_HEADS 32
#define HEAD_DIM 64
#define NUM_KV 8
#define GROUP_SIZE 4
#define D_KV (NUM_KV * HEAD_DIM)   // 512
#define ROWS (BATCH * SEQ)         // 4096

// Scratch buffers (device globals; no runtime allocation allowed)
__device__ float g_Q[(size_t)ROWS * D_OUT];   // 33.5 MB
__device__ float g_K[(size_t)ROWS * D_KV];    // 8.4 MB
__device__ float g_V[(size_t)ROWS * D_KV];    // 8.4 MB
__device__ float g_CTX[(size_t)ROWS * D_OUT]; // 33.5 MB

// ---------------------------------------------------------------------------
// Tiled FP32 GEMM: C[M,N] = A[M,K] * B[K,N]. BM=BN=64, BK=16, 256 threads,
// 4x4 outputs per thread. Dimensions are exact multiples of tiles here.
// ---------------------------------------------------------------------------
__global__ __launch_bounds__(256) void gemm64(
    const float* __restrict__ A, const float* __restrict__ B,
    float* __restrict__ C, int M, int N, int K)
{
    __shared__ float As[16][64];  // As[k][m]
    __shared__ float Bs[16][64];  // Bs[k][n]

    const int tid = threadIdx.x;
    const int tx = tid & 15;        // 0..15  (n dir)
    const int ty = tid >> 4;        // 0..15  (m dir)
    const int m0 = blockIdx.y * 64;
    const int n0 = blockIdx.x * 64;

    float acc[4][4];
#pragma unroll
    for (int i = 0; i < 4; i++)
#pragma unroll
        for (int j = 0; j < 4; j++) acc[i][j] = 0.f;

    for (int kt = 0; kt < K; kt += 16) {
        // Load A tile (64 rows x 16 k) transposed into As[k][m]
#pragma unroll
        for (int e = 0; e < 4; e++) {
            int idx = e * 256 + tid;          // 0..1023
            int ar = idx >> 4;                // 0..63
            int ac = idx & 15;                // 0..15
            As[ac][ar] = A[(size_t)(m0 + ar) * K + kt + ac];
        }
        // Load B tile (16 k x 64 n)
#pragma unroll
        for (int e = 0; e < 4; e++) {
            int idx = e * 256 + tid;
            int br = idx >> 6;                // 0..15
            int bc = idx & 63;                // 0..63
            Bs[br][bc] = B[(size_t)(kt + br) * N + n0 + bc];
        }
        __syncthreads();

#pragma unroll
        for (int kk = 0; kk < 16; kk++) {
            float a[4], b[4];
#pragma unroll
            for (int i = 0; i < 4; i++) a[i] = As[kk][ty * 4 + i];
#pragma unroll
            for (int j = 0; j < 4; j++) b[j] = Bs[kk][tx * 4 + j];
#pragma unroll
            for (int i = 0; i < 4; i++)
#pragma unroll
                for (int j = 0; j < 4; j++)
                    acc[i][j] += a[i] * b[j];
        }
        __syncthreads();
    }

#pragma unroll
    for (int i = 0; i < 4; i++) {
        size_t row = (size_t)(m0 + ty * 4 + i) * N + n0 + tx * 4;
#pragma unroll
        for (int j = 0; j < 4; j++)
            C[row + j] = acc[i][j];
    }
}

// ---------------------------------------------------------------------------
// RoPE in-place on T of shape (ROWS, nHeads*64). One thread per (row, h, d<32).
// ---------------------------------------------------------------------------
__global__ void rope_kernel(float* __restrict__ T,
                            const float* __restrict__ cosT,
                            const float* __restrict__ sinT,
                            int nHeads, int total)
{
    int idx = blockIdx.x * blockDim.x + threadIdx.x;
    if (idx >= total) return;
    int per_row = nHeads * 32;
    int row = idx / per_row;
    int r = idx - row * per_row;
    int h = r >> 5;
    int d = r & 31;
    int s = row & (SEQ - 1);   // row % SEQ  (SEQ is pow2)

    float* p = T + (size_t)row * (nHeads * 64) + h * 64;
    float x1 = p[d];
    float x2 = p[d + 32];
    float c1 = cosT[s * 64 + d];
    float s1 = sinT[s * 64 + d];
    float c2 = cosT[s * 64 + d + 32];
    float s2 = sinT[s * 64 + d + 32];
    p[d]      = x1 * c1 - x2 * s1;  // rotated[:32] = -x2
    p[d + 32] = x2 * c2 + x1 * s2;  // rotated[32:] = x1
}

// ---------------------------------------------------------------------------
// Causal flash attention. One thread per query row; 128 rows per block.
// grid = (SEQ/128, NUM_HEADS, BATCH). K/V tiles of 64 keys staged in smem.
// ---------------------------------------------------------------------------
__global__ __launch_bounds__(128) void attn_kernel(
    const float* __restrict__ Q, const float* __restrict__ K,
    const float* __restrict__ V, float* __restrict__ CTX)
{
    __shared__ float Ks[64][64];
    __shared__ float Vs[64][64];

    const int tid = threadIdx.x;
    const int qt = blockIdx.x;
    const int h = blockIdx.y;
    const int b = blockIdx.z;
    const int g = h >> 2;                 // kv group (GROUP_SIZE = 4)
    const int qrow = qt * 128 + tid;      // 0..SEQ-1

    const float* qp = Q + ((size_t)(b * SEQ + qrow)) * D_OUT + h * HEAD_DIM;
    float q[64];
#pragma unroll
    for (int i = 0; i < 64; i++) q[i] = qp[i] * 0.125f;  // 1/sqrt(64)

    float m = -INFINITY;
    float l = 0.f;
    float acc[64];
#pragma unroll
    for (int i = 0; i < 64; i++) acc[i] = 0.f;

    const int kmax = qt * 128 + 127;  // largest query row in this block

    for (int kb = 0; kb <= kmax; kb += 64) {
        __syncthreads();
        // cooperative load of 64x64 K and V tiles
        for (int i = tid; i < 64 * 64; i += 128) {
            int kk = i >> 6;
            int d  = i & 63;
            size_t src = ((size_t)(b * SEQ + kb + kk)) * D_KV + g * HEAD_DIM + d;
            Ks[kk][d] = K[src];
            Vs[kk][d] = V[src];
        }
        __syncthreads();

        int lim = qrow - kb + 1;
        if (lim > 64) lim = 64;
        for (int kk = 0; kk < lim; kk++) {
            const float4* kr = reinterpret_cast<const float4*>(&Ks[kk][0]);
            float s = 0.f;
#pragma unroll
            for (int d4 = 0; d4 < 16; d4++) {
                float4 kv = kr[d4];
                s += q[d4 * 4 + 0] * kv.x;
                s += q[d4 * 4 + 1] * kv.y;
                s += q[d4 * 4 + 2] * kv.z;
                s += q[d4 * 4 + 3] * kv.w;
            }
            if (s > m) {
                float corr = __expf(m - s);
                l *= corr;
#pragma unroll
                for (int d = 0; d < 64; d++) acc[d] *= corr;
                m = s;
            }
            float p = __expf(s - m);
            l += p;
            const float4* vr = reinterpret_cast<const float4*>(&Vs[kk][0]);
#pragma unroll
            for (int d4 = 0; d4 < 16; d4++) {
                float4 vv = vr[d4];
                acc[d4 * 4 + 0] += p * vv.x;
                acc[d4 * 4 + 1] += p * vv.y;
                acc[d4 * 4 + 2] += p * vv.z;
                acc[d4 * 4 + 3] += p * vv.w;
            }
        }
    }

    float inv = 1.f / l;
    float* op = CTX + ((size_t)(b * SEQ + qrow)) * D_OUT + h * HEAD_DIM;
#pragma unroll
    for (int i = 0; i < 64; i++) op[i] = acc[i] * inv;
}

// ---------------------------------------------------------------------------
// kernel_launch
// inputs: x, cos, sin, mask(unused — causal computed inline), Wq, Wk, Wv, Wo
// ---------------------------------------------------------------------------
extern "C" void kernel_launch(void* const* d_in, const int* in_sizes, int n_in,
                              void* d_out, int out_size)
{
    const float* x    = (const float*)d_in[0];
    const float* cosT = (const float*)d_in[1];
    const float* sinT = (const float*)d_in[2];
    const float* Wq   = (const float*)d_in[4];
    const float* Wk   = (const float*)d_in[5];
    const float* Wv   = (const float*)d_in[6];
    const float* Wo   = (const float*)d_in[7];
    float* out = (float*)d_out;

    float *Q, *K, *V, *CTX;
    cudaGetSymbolAddress((void**)&Q,   g_Q);
    cudaGetSymbolAddress((void**)&K,   g_K);
    cudaGetSymbolAddress((void**)&V,   g_V);
    cudaGetSymbolAddress((void**)&CTX, g_CTX);

    // Projections
    gemm64<<<dim3(D_OUT / 64, ROWS / 64), 256>>>(x, Wq, Q, ROWS, D_OUT, D_IN);
    gemm64<<<dim3(D_KV  / 64, ROWS / 64), 256>>>(x, Wk, K, ROWS, D_KV, D_IN);
    gemm64<<<dim3(D_KV  / 64, ROWS / 64), 256>>>(x, Wv, V, ROWS, D_KV, D_IN);

    // RoPE
    {
        int totQ = ROWS * NUM_HEADS * 32;
        rope_kernel<<<(totQ + 255) / 256, 256>>>(Q, cosT, sinT, NUM_HEADS, totQ);
        int totK = ROWS * NUM_KV * 32;
        rope_kernel<<<(totK + 255) / 256, 256>>>(K, cosT, sinT, NUM_KV, totK);
    }

    // Attention
    attn_kernel<<<dim3(SEQ / 128, NUM_HEADS, BATCH), 128>>>(Q, K, V, CTX);

    // Output projection
    gemm64<<<dim3(D_OUT / 64, ROWS / 64), 256>>>(CTX, Wo, out, ROWS, D_OUT, D_IN);
}

// round 3
// speedup vs baseline: 2.6732x; 2.6732x over previous
#include <cuda_runtime.h>
#include <math.h>
#include <stdint.h>

// ---------------- problem constants ----------------
#define BATCH 2
#define SEQ   2048
#define DIN   2048
#define DOUT  2048
#define NH    32
#define HD    64
#define NKV   8
#define ROWS  4096          // BATCH*SEQ
#define DKV   1024          // K(512) | V(512) packed per row

// ---------------- scratch (device globals; no runtime alloc) ----------------
__device__ float g_Q  [(size_t)ROWS * DOUT];
__device__ float g_KV [(size_t)ROWS * DKV];
__device__ float g_CTX[(size_t)ROWS * DOUT];
__device__ float g_WqT [(size_t)DOUT * DIN];   // [N][K] K-major
__device__ float g_WkvT[(size_t)DKV  * DIN];   // rows 0-511 Wk^T, 512-1023 Wv^T
__device__ float g_WoT [(size_t)DOUT * DIN];

// ---------------- helpers ----------------
__device__ __forceinline__ uint32_t smem_u32(const void* p) {
    uint32_t a;
    asm("{ .reg .u64 t; cvta.to.shared.u64 t, %1; cvt.u32.u64 %0, t; }" : "=r"(a) : "l"(p));
    return a;
}
__device__ __forceinline__ void cp16(uint32_t dst, const void* src) {
    asm volatile("cp.async.cg.shared.global [%0], [%1], 16;" :: "r"(dst), "l"(src) : "memory");
}
__device__ __forceinline__ void cp_commit() { asm volatile("cp.async.commit_group;" ::: "memory"); }
template<int N> __device__ __forceinline__ void cp_wait() {
    asm volatile("cp.async.wait_group %0;" :: "n"(N) : "memory");
}
__device__ __forceinline__ uint32_t f2tf32(float f) {
    uint32_t u; asm("cvt.rna.tf32.f32 %0, %1;" : "=r"(u) : "f"(f)); return u;
}
__device__ __forceinline__ void mma1688(float* d, const uint32_t* a, const uint32_t* b) {
    asm volatile("mma.sync.aligned.m16n8k8.row.col.f32.tf32.tf32.f32 "
        "{%0,%1,%2,%3}, {%4,%5,%6,%7}, {%8,%9}, {%0,%1,%2,%3};"
        : "+f"(d[0]), "+f"(d[1]), "+f"(d[2]), "+f"(d[3])
        : "r"(a[0]), "r"(a[1]), "r"(a[2]), "r"(a[3]), "r"(b[0]), "r"(b[1]));
}

// packed f32x2 ops (Blackwell dual-rate fp32)
typedef unsigned long long u64;
__device__ __forceinline__ u64 pack2(float lo, float hi) {
    u64 r; asm("mov.b64 %0, {%1, %2};" : "=l"(r) : "f"(lo), "f"(hi)); return r;
}
__device__ __forceinline__ void unpack2(u64 v, float& lo, float& hi) {
    asm("mov.b64 {%0, %1}, %2;" : "=f"(lo), "=f"(hi) : "l"(v));
}
__device__ __forceinline__ u64 fma2(u64 a, u64 b, u64 c) {
    u64 d; asm("fma.rn.f32x2 %0, %1, %2, %3;" : "=l"(d) : "l"(a), "l"(b), "l"(c)); return d;
}
__device__ __forceinline__ u64 mul2(u64 a, u64 b) {
    u64 d; asm("mul.rn.f32x2 %0, %1, %2;" : "=l"(d) : "l"(a), "l"(b)); return d;
}

// ---------------- transpose: in[K][N] -> out[N][K] ----------------
__global__ void transpose_k(const float* __restrict__ in, float* __restrict__ out,
                            int K, int N) {
    __shared__ float t[32][33];
    int nb = blockIdx.x * 32, kb = blockIdx.y * 32;
    int tx = threadIdx.x, ty = threadIdx.y; // 32 x 8
#pragma unroll
    for (int i = 0; i < 32; i += 8)
        t[ty + i][tx] = in[(size_t)(kb + ty + i) * N + nb + tx];
    __syncthreads();
#pragma unroll
    for (int i = 0; i < 32; i += 8)
        out[(size_t)(nb + ty + i) * K + kb + tx] = t[tx][ty + i];
}

// ---------------- tf32 mma.sync GEMM: C[M,Ntot] = A[M,2048] * B[Ntot,2048]^T --
// CTA 128x128, BK=32, 3-stage cp.async, 8 warps (warp tile 64x32).
#define BM 128
#define BN 128
#define BK 32
#define NSTG 3
#define KITER (DIN / BK)                 // 64
#define APAD 4
#define ASTRIDE (BK + APAD)              // 36 floats
#define TILE_FLOATS (128 * ASTRIDE)      // per operand per stage
#define STAGE_FLOATS (2 * TILE_FLOATS)
#define GEMM_SMEM (NSTG * STAGE_FLOATS * 4)

__device__ __forceinline__ void load_stage(const float* __restrict__ A,
                                           const float* __restrict__ B,
                                           float* sA, float* sB,
                                           int m0, int n0, int k0, int tid) {
    uint32_t a_s = smem_u32(sA), b_s = smem_u32(sB);
#pragma unroll
    for (int t = 0; t < 4; ++t) {         // A: 128 rows x 8 chunks of 16B
        int idx = t * 256 + tid;
        int r = idx >> 3, c = idx & 7;
        cp16(a_s + (r * ASTRIDE + c * 4) * 4, A + (size_t)(m0 + r) * DIN + k0 + c * 4);
    }
#pragma unroll
    for (int t = 0; t < 4; ++t) {         // B: 128 rows x 8 chunks
        int idx = t * 256 + tid;
        int r = idx >> 3, c = idx & 7;
        cp16(b_s + (r * ASTRIDE + c * 4) * 4, B + (size_t)(n0 + r) * DIN + k0 + c * 4);
    }
    cp_commit();
}

__global__ __launch_bounds__(256, 1) void gemm_tf32(const float* __restrict__ A,
                                                    const float* __restrict__ B,
                                                    float* __restrict__ C, int Ntot) {
    extern __shared__ float smem[];
    const int tid  = threadIdx.x;
    const int lane = tid & 31;
    const int warp = tid >> 5;
    const int wm = warp & 1;              // 2 warps in m
    const int wn = warp >> 1;             // 4 warps in n
    const int gid = lane >> 2;            // 0..7
    const int tig = lane & 3;             // 0..3
    const int m0 = blockIdx.y * BM;
    const int n0 = blockIdx.x * BN;

    float acc[4][4][4];
#pragma unroll
    for (int i = 0; i < 4; ++i)
#pragma unroll
        for (int j = 0; j < 4; ++j)
#pragma unroll
            for (int r = 0; r < 4; ++r) acc[i][j][r] = 0.f;

    // prologue: fill NSTG-1 stages
#pragma unroll
    for (int s = 0; s < NSTG - 1; ++s)
        load_stage(A, B, smem + s * STAGE_FLOATS, smem + s * STAGE_FLOATS + TILE_FLOATS,
                   m0, n0, s * BK, tid);
    int load_it = NSTG - 1;

    for (int it = 0; it < KITER; ++it) {
        if (load_it < KITER) {
            int s = load_it % NSTG;
            load_stage(A, B, smem + s * STAGE_FLOATS, smem + s * STAGE_FLOATS + TILE_FLOATS,
                       m0, n0, load_it * BK, tid);
            ++load_it;
        }
        cp_wait<NSTG - 1>();
        __syncthreads();

        const float* sA = smem + (it % NSTG) * STAGE_FLOATS;
        const float* sB = sA + TILE_FLOATS;

#pragma unroll
        for (int ks = 0; ks < BK / 8; ++ks) {
            const int kc = ks * 8;
            uint32_t af[4][4], bf[4][2];
#pragma unroll
            for (int mt = 0; mt < 4; ++mt) {
                const float* ap = sA + (wm * 64 + mt * 16 + gid) * ASTRIDE + kc + tig;
                af[mt][0] = f2tf32(ap[0]);
                af[mt][1] = f2tf32(ap[8 * ASTRIDE]);
                af[mt][2] = f2tf32(ap[4]);
                af[mt][3] = f2tf32(ap[8 * ASTRIDE + 4]);
            }
#pragma unroll
            for (int nt = 0; nt < 4; ++nt) {
                const float* bp = sB + (wn * 32 + nt * 8 + gid) * ASTRIDE + kc + tig;
                bf[nt][0] = f2tf32(bp[0]);
                bf[nt][1] = f2tf32(bp[4]);
            }
#pragma unroll
            for (int mt = 0; mt < 4; ++mt)
#pragma unroll
                for (int nt = 0; nt < 4; ++nt)
                    mma1688(acc[mt][nt], af[mt], bf[nt]);
        }
        __syncthreads();
    }

    // epilogue
#pragma unroll
    for (int mt = 0; mt < 4; ++mt) {
        const int row = m0 + wm * 64 + mt * 16 + gid;
#pragma unroll
        for (int nt = 0; nt < 4; ++nt) {
            const int col = n0 + wn * 32 + nt * 8 + 2 * tig;
            float2 v0 = make_float2(acc[mt][nt][0], acc[mt][nt][1]);
            float2 v1 = make_float2(acc[mt][nt][2], acc[mt][nt][3]);
            *(float2*)(C + (size_t)row * Ntot + col)       = v0;
            *(float2*)(C + (size_t)(row + 8) * Ntot + col) = v1;
        }
    }
}

// ---------------- RoPE (in place), row stride parametrized ----------------
__global__ void rope_kernel(float* __restrict__ T, const float* __restrict__ cosT,
                            const float* __restrict__ sinT, int rowStride,
                            int nHeads, int total) {
    int idx = blockIdx.x * blockDim.x + threadIdx.x;
    if (idx >= total) return;
    int per_row = nHeads * 32;
    int row = idx / per_row;
    int r = idx - row * per_row;
    int h = r >> 5;
    int d = r & 31;
    int s = row & (SEQ - 1);

    float* p = T + (size_t)row * rowStride + h * 64;
    float x1 = p[d], x2 = p[d + 32];
    float c1 = cosT[s * 64 + d],      s1 = sinT[s * 64 + d];
    float c2 = cosT[s * 64 + d + 32], s2 = sinT[s * 64 + d + 32];
    p[d]      = x1 * c1 - x2 * s1;
    p[d + 32] = x2 * c2 + x1 * s2;
}

// ---------------- causal flash attention (fp32, packed f32x2 math) --------
__global__ __launch_bounds__(128) void attn_kernel(const float* __restrict__ Q,
                                                   const float* __restrict__ KV,
                                                   float* __restrict__ CTX) {
    __shared__ float Ks[64][64];
    __shared__ float Vs[64][64];

    const int tid = threadIdx.x;
    const int qt = blockIdx.x;
    const int h = blockIdx.y;
    const int b = blockIdx.z;
    const int g = h >> 2;                 // kv group
    const int qrow = qt * 128 + tid;

    const float4* qp4 = (const float4*)(Q + (size_t)(b * SEQ + qrow) * DOUT + h * HD);
    u64 q2[32];
#pragma unroll
    for (int i = 0; i < 16; ++i) {
        float4 v = qp4[i];
        q2[2 * i]     = pack2(v.x * 0.125f, v.y * 0.125f);
        q2[2 * i + 1] = pack2(v.z * 0.125f, v.w * 0.125f);
    }

    float m = -INFINITY, l = 0.f;
    u64 acc2[32];
#pragma unroll
    for (int i = 0; i < 32; ++i) acc2[i] = 0ull;

    const int kmax = qt * 128 + 127;
    for (int kb = 0; kb <= kmax; kb += 64) {
        __syncthreads();
        for (int i = tid; i < 64 * 16; i += 128) {
            int kk = i >> 4, d4 = i & 15;
            const float4* src = (const float4*)(KV + (size_t)(b * SEQ + kb + kk) * DKV + g * HD);
            ((float4*)&Ks[kk][0])[d4] = src[d4];
            ((float4*)&Vs[kk][0])[d4] = src[d4 + 128];
        }
        __syncthreads();

        int lim = qrow - kb + 1;
        if (lim > 64) lim = 64;
        for (int kk = 0; kk < lim; ++kk) {
            const float4* kr = (const float4*)&Ks[kk][0];
            u64 s2a = 0ull, s2b = 0ull;
#pragma unroll
            for (int d4 = 0; d4 < 16; ++d4) {
                float4 kv = kr[d4];
                s2a = fma2(pack2(kv.x, kv.y), q2[2 * d4],     s2a);
                s2b = fma2(pack2(kv.z, kv.w), q2[2 * d4 + 1], s2b);
            }
            float sa, sb, sc, sd;
            unpack2(s2a, sa, sb); unpack2(s2b, sc, sd);
            float s = (sa + sb) + (sc + sd);

            if (s > m) {
                float corr = __expf(m - s);
                l *= corr;
                u64 c2 = pack2(corr, corr);
#pragma unroll
                for (int i = 0; i < 32; ++i) acc2[i] = mul2(acc2[i], c2);
                m = s;
            }
            float p = __expf(s - m);
            l += p;
            u64 p2 = pack2(p, p);
            const float4* vr = (const float4*)&Vs[kk][0];
#pragma unroll
            for (int d4 = 0; d4 < 16; ++d4) {
                float4 vv = vr[d4];
                acc2[2 * d4]     = fma2(p2, pack2(vv.x, vv.y), acc2[2 * d4]);
                acc2[2 * d4 + 1] = fma2(p2, pack2(vv.z, vv.w), acc2[2 * d4 + 1]);
            }
        }
    }

    float inv = 1.f / l;
    float4* op4 = (float4*)(CTX + (size_t)(b * SEQ + qrow) * DOUT + h * HD);
#pragma unroll
    for (int i = 0; i < 16; ++i) {
        float a0, a1, a2, a3;
        unpack2(acc2[2 * i], a0, a1);
        unpack2(acc2[2 * i + 1], a2, a3);
        float4 v; v.x = a0 * inv; v.y = a1 * inv; v.z = a2 * inv; v.w = a3 * inv;
        op4[i] = v;
    }
}

// ---------------- kernel_launch ----------------
extern "C" void kernel_launch(void* const* d_in, const int* in_sizes, int n_in,
                              void* d_out, int out_size) {
    const float* x    = (const float*)d_in[0];
    const float* cosT = (const float*)d_in[1];
    const float* sinT = (const float*)d_in[2];
    const float* Wq   = (const float*)d_in[4];
    const float* Wk   = (const float*)d_in[5];
    const float* Wv   = (const float*)d_in[6];
    const float* Wo   = (const float*)d_in[7];
    float* out = (float*)d_out;

    float *Q, *KV, *CTX, *WqT, *WkvT, *WoT;
    cudaGetSymbolAddress((void**)&Q,    g_Q);
    cudaGetSymbolAddress((void**)&KV,   g_KV);
    cudaGetSymbolAddress((void**)&CTX,  g_CTX);
    cudaGetSymbolAddress((void**)&WqT,  g_WqT);
    cudaGetSymbolAddress((void**)&WkvT, g_WkvT);
    cudaGetSymbolAddress((void**)&WoT,  g_WoT);

    cudaFuncSetAttribute(gemm_tf32, cudaFuncAttributeMaxDynamicSharedMemorySize, GEMM_SMEM);

    // transpose weights to K-major [N][2048]
    transpose_k<<<dim3(DOUT / 32, DIN / 32), dim3(32, 8)>>>(Wq, WqT, DIN, DOUT);
    transpose_k<<<dim3(512  / 32, DIN / 32), dim3(32, 8)>>>(Wk, WkvT,                      DIN, 512);
    transpose_k<<<dim3(512  / 32, DIN / 32), dim3(32, 8)>>>(Wv, WkvT + (size_t)512 * DIN,  DIN, 512);
    transpose_k<<<dim3(DOUT / 32, DIN / 32), dim3(32, 8)>>>(Wo, WoT, DIN, DOUT);

    // projections (tf32 tensor cores via mma.sync)
    gemm_tf32<<<dim3(DOUT / BN, ROWS / BM), 256, GEMM_SMEM>>>(x, WqT,  Q,  DOUT);
    gemm_tf32<<<dim3(DKV  / BN, ROWS / BM), 256, GEMM_SMEM>>>(x, WkvT, KV, DKV);

    // RoPE on Q and on K half of KV
    int totQ = ROWS * NH * 32;
    rope_kernel<<<(totQ + 255) / 256, 256>>>(Q, cosT, sinT, DOUT, NH, totQ);
    int totK = ROWS * NKV * 32;
    rope_kernel<<<(totK + 255) / 256, 256>>>(KV, cosT, sinT, DKV, NKV, totK);

    // attention
    attn_kernel<<<dim3(SEQ / 128, NH, BATCH), 128>>>(Q, KV, CTX);

    // output projection
    gemm_tf32<<<dim3(DOUT / BN, ROWS / BM), 256, GEMM_SMEM>>>(CTX, WoT, out, DOUT);
}

// round 5
// speedup vs baseline: 3.4391x; 1.2865x over previous
#include <cuda_runtime.h>
#include <math.h>
#include <stdint.h>

// ---------------- problem constants ----------------
#define BATCH 2
#define SEQ   2048
#define DIN   2048
#define DOUT  2048
#define NH    32
#define HD    64
#define NKV   8
#define ROWS  4096          // BATCH*SEQ
#define DKV   1024          // K(512) | V(512) packed per row

// ---------------- scratch (device globals; no runtime alloc) ----------------
__device__ float g_Q  [(size_t)ROWS * DOUT];
__device__ float g_KV [(size_t)ROWS * DKV];
__device__ float g_CTX[(size_t)ROWS * DOUT];
__device__ float g_WqT [(size_t)DOUT * DIN];   // [N][K] K-major
__device__ float g_WkvT[(size_t)DKV  * DIN];   // rows 0-511 Wk^T, 512-1023 Wv^T
__device__ float g_WoT [(size_t)DOUT * DIN];

// ---------------- helpers ----------------
__device__ __forceinline__ uint32_t smem_u32(const void* p) {
    uint32_t a;
    asm("{ .reg .u64 t; cvta.to.shared.u64 t, %1; cvt.u32.u64 %0, t; }" : "=r"(a) : "l"(p));
    return a;
}
__device__ __forceinline__ void cp16(uint32_t dst, const void* src) {
    asm volatile("cp.async.cg.shared.global [%0], [%1], 16;" :: "r"(dst), "l"(src) : "memory");
}
__device__ __forceinline__ void cp_commit() { asm volatile("cp.async.commit_group;" ::: "memory"); }
template<int N> __device__ __forceinline__ void cp_wait() {
    asm volatile("cp.async.wait_group %0;" :: "n"(N) : "memory");
}
__device__ __forceinline__ uint32_t f2tf32(float f) {
    uint32_t u; asm("cvt.rna.tf32.f32 %0, %1;" : "=r"(u) : "f"(f)); return u;
}
__device__ __forceinline__ float ex2(float x) {
    float y; asm("ex2.approx.ftz.f32 %0, %1;" : "=f"(y) : "f"(x)); return y;
}
__device__ __forceinline__ void mma1688(float* d, const uint32_t* a, const uint32_t* b) {
    asm volatile("mma.sync.aligned.m16n8k8.row.col.f32.tf32.tf32.f32 "
        "{%0,%1,%2,%3}, {%4,%5,%6,%7}, {%8,%9}, {%0,%1,%2,%3};"
        : "+f"(d[0]), "+f"(d[1]), "+f"(d[2]), "+f"(d[3])
        : "r"(a[0]), "r"(a[1]), "r"(a[2]), "r"(a[3]), "r"(b[0]), "r"(b[1]));
}

// ---------------- transpose: in[K][N] -> out[N][K] ----------------
__global__ void transpose_k(const float* __restrict__ in, float* __restrict__ out,
                            int K, int N) {
    __shared__ float t[32][33];
    int nb = blockIdx.x * 32, kb = blockIdx.y * 32;
    int tx = threadIdx.x, ty = threadIdx.y; // 32 x 8
#pragma unroll
    for (int i = 0; i < 32; i += 8)
        t[ty + i][tx] = in[(size_t)(kb + ty + i) * N + nb + tx];
    __syncthreads();
#pragma unroll
    for (int i = 0; i < 32; i += 8)
        out[(size_t)(nb + ty + i) * K + kb + tx] = t[tx][ty + i];
}

// ---------------- tf32 mma.sync GEMM (2-term A-split): C = A*B^T --------------
// CTA 128x128, BK=32, 3-stage cp.async, 8 warps (warp tile 64x32).
#define BM 128
#define BN 128
#define BK 32
#define NSTG 3
#define KITER (DIN / BK)                 // 64
#define APAD 4
#define ASTRIDE (BK + APAD)              // 36 floats
#define TILE_FLOATS (128 * ASTRIDE)
#define STAGE_FLOATS (2 * TILE_FLOATS)
#define GEMM_SMEM (NSTG * STAGE_FLOATS * 4)

__device__ __forceinline__ void load_stage(const float* __restrict__ A,
                                           const float* __restrict__ B,
                                           float* sA, float* sB,
                                           int m0, int n0, int k0, int tid) {
    uint32_t a_s = smem_u32(sA), b_s = smem_u32(sB);
#pragma unroll
    for (int t = 0; t < 4; ++t) {
        int idx = t * 256 + tid;
        int r = idx >> 3, c = idx & 7;
        cp16(a_s + (r * ASTRIDE + c * 4) * 4, A + (size_t)(m0 + r) * DIN + k0 + c * 4);
    }
#pragma unroll
    for (int t = 0; t < 4; ++t) {
        int idx = t * 256 + tid;
        int r = idx >> 3, c = idx & 7;
        cp16(b_s + (r * ASTRIDE + c * 4) * 4, B + (size_t)(n0 + r) * DIN + k0 + c * 4);
    }
    cp_commit();
}

__global__ __launch_bounds__(256, 1) void gemm_tf32(const float* __restrict__ A,
                                                    const float* __restrict__ B,
                                                    float* __restrict__ C, int Ntot) {
    extern __shared__ float smem[];
    const int tid  = threadIdx.x;
    const int lane = tid & 31;
    const int warp = tid >> 5;
    const int wm = warp & 1;
    const int wn = warp >> 1;
    const int gid = lane >> 2;
    const int tig = lane & 3;
    const int m0 = blockIdx.y * BM;
    const int n0 = blockIdx.x * BN;

    float acc[4][4][4];
#pragma unroll
    for (int i = 0; i < 4; ++i)
#pragma unroll
        for (int j = 0; j < 4; ++j)
#pragma unroll
            for (int r = 0; r < 4; ++r) acc[i][j][r] = 0.f;

#pragma unroll
    for (int s = 0; s < NSTG - 1; ++s)
        load_stage(A, B, smem + s * STAGE_FLOATS, smem + s * STAGE_FLOATS + TILE_FLOATS,
                   m0, n0, s * BK, tid);
    int load_it = NSTG - 1;

    for (int it = 0; it < KITER; ++it) {
        if (load_it < KITER) {
            int s = load_it % NSTG;
            load_stage(A, B, smem + s * STAGE_FLOATS, smem + s * STAGE_FLOATS + TILE_FLOATS,
                       m0, n0, load_it * BK, tid);
            ++load_it;
        }
        cp_wait<NSTG - 1>();
        __syncthreads();

        const float* sA = smem + (it % NSTG) * STAGE_FLOATS;
        const float* sB = sA + TILE_FLOATS;

#pragma unroll
        for (int ks = 0; ks < BK / 8; ++ks) {
            const int kc = ks * 8;
            uint32_t af[4][4], al[4][4], bf[4][2];
#pragma unroll
            for (int mt = 0; mt < 4; ++mt) {
                const float* ap = sA + (wm * 64 + mt * 16 + gid) * ASTRIDE + kc + tig;
                float v0 = ap[0], v1 = ap[8 * ASTRIDE], v2 = ap[4], v3 = ap[8 * ASTRIDE + 4];
                af[mt][0] = f2tf32(v0); al[mt][0] = f2tf32(v0 - __uint_as_float(af[mt][0]));
                af[mt][1] = f2tf32(v1); al[mt][1] = f2tf32(v1 - __uint_as_float(af[mt][1]));
                af[mt][2] = f2tf32(v2); al[mt][2] = f2tf32(v2 - __uint_as_float(af[mt][2]));
                af[mt][3] = f2tf32(v3); al[mt][3] = f2tf32(v3 - __uint_as_float(af[mt][3]));
            }
#pragma unroll
            for (int nt = 0; nt < 4; ++nt) {
                const float* bp = sB + (wn * 32 + nt * 8 + gid) * ASTRIDE + kc + tig;
                bf[nt][0] = f2tf32(bp[0]);
                bf[nt][1] = f2tf32(bp[4]);
            }
#pragma unroll
            for (int mt = 0; mt < 4; ++mt)
#pragma unroll
                for (int nt = 0; nt < 4; ++nt) {
                    mma1688(acc[mt][nt], af[mt], bf[nt]);
                    mma1688(acc[mt][nt], al[mt], bf[nt]);
                }
        }
        __syncthreads();
    }

#pragma unroll
    for (int mt = 0; mt < 4; ++mt) {
        const int row = m0 + wm * 64 + mt * 16 + gid;
#pragma unroll
        for (int nt = 0; nt < 4; ++nt) {
            const int col = n0 + wn * 32 + nt * 8 + 2 * tig;
            *(float2*)(C + (size_t)row * Ntot + col)       = make_float2(acc[mt][nt][0], acc[mt][nt][1]);
            *(float2*)(C + (size_t)(row + 8) * Ntot + col) = make_float2(acc[mt][nt][2], acc[mt][nt][3]);
        }
    }
}

// ---------------- RoPE (in place) ----------------
__global__ void rope_kernel(float* __restrict__ T, const float* __restrict__ cosT,
                            const float* __restrict__ sinT, int rowStride,
                            int nHeads, int total) {
    int idx = blockIdx.x * blockDim.x + threadIdx.x;
    if (idx >= total) return;
    int per_row = nHeads * 32;
    int row = idx / per_row;
    int r = idx - row * per_row;
    int h = r >> 5;
    int d = r & 31;
    int s = row & (SEQ - 1);

    float* p = T + (size_t)row * rowStride + h * 64;
    float x1 = p[d], x2 = p[d + 32];
    float c1 = cosT[s * 64 + d],      s1 = sinT[s * 64 + d];
    float c2 = cosT[s * 64 + d + 32], s2 = sinT[s * 64 + d + 32];
    p[d]      = x1 * c1 - x2 * s1;
    p[d + 32] = x2 * c2 + x1 * s2;
}

// ---------------- tensor-core causal flash attention (tf32 mma.sync) ------
// CTA: 128 query rows of one (b,h). 8 warps, 16 rows/warp. KV tiles of 64 keys,
// double-buffered cp.async. Softmax in fragment layout; P->A-frag via quad shfl.
#define QSTR 68
#define KSTR 68
#define VSTR 72
#define ATT_QF   (128 * QSTR)
#define ATT_KF   (64 * KSTR)
#define ATT_VF   (64 * VSTR)
#define ATT_SMEM ((ATT_QF + 2 * ATT_KF + 2 * ATT_VF) * 4)
#define CS 0.1803368801111244f   // 0.125 / ln(2)

__device__ __forceinline__ void attn_load_kv(const float* __restrict__ KV,
                                             float* sK, float* sV,
                                             int b, int g, int kb, int tid) {
    // K tile: 64 rows x 16 float4 chunks = 1024 chunks; 256 threads -> 4 iters
    uint32_t k_s = smem_u32(sK), v_s = smem_u32(sV);
#pragma unroll
    for (int t = 0; t < 4; ++t) {
        int idx = t * 256 + tid;
        int r = idx >> 4, c = idx & 15;
        const float* src = KV + (size_t)(b * SEQ + kb + r) * DKV + g * HD + c * 4;
        cp16(k_s + (r * KSTR + c * 4) * 4, src);
        cp16(v_s + (r * VSTR + c * 4) * 4, src + 512);
    }
    cp_commit();
}

__global__ __launch_bounds__(256) void attn_tc(const float* __restrict__ Q,
                                               const float* __restrict__ KV,
                                               float* __restrict__ CTX) {
    extern __shared__ float sm[];
    float* sQ = sm;
    float* sK = sm + ATT_QF;
    float* sV = sm + ATT_QF + 2 * ATT_KF;

    const int tid = threadIdx.x;
    const int lane = tid & 31;
    const int w = tid >> 5;
    const int gid = lane >> 2;
    const int tig = lane & 3;
    const int qt = blockIdx.x;
    const int h = blockIdx.y;
    const int b = blockIdx.z;
    const int g = h >> 2;

    // load Q tile (128 rows x 16 float4 chunks = 2048 chunks; 8 iters)
    {
        uint32_t q_s = smem_u32(sQ);
#pragma unroll
        for (int t = 0; t < 8; ++t) {
            int idx = t * 256 + tid;
            int r = idx >> 4, c = idx & 15;
            cp16(q_s + (r * QSTR + c * 4) * 4,
                 Q + (size_t)(b * SEQ + qt * 128 + r) * DOUT + h * HD + c * 4);
        }
    }
    cp_commit();
    cp_wait<0>();
    __syncthreads();
    // pre-scale by 0.125/ln2 (exp -> exp2)
    for (int i = tid; i < 128 * 64; i += 256)
        sQ[(i >> 6) * QSTR + (i & 63)] *= CS;
    __syncthreads();

    const int q0 = qt * 128 + w * 16;       // first global row of this warp
    float m0 = -1e30f, m1 = -1e30f, l0 = 0.f, l1 = 0.f;
    float oa[8][4];
#pragma unroll
    for (int j = 0; j < 8; ++j)
#pragma unroll
        for (int r = 0; r < 4; ++r) oa[j][r] = 0.f;

    const float* sQw = sQ + (w * 16 + gid) * QSTR;

    const int T = 2 * qt + 2;               // KV tiles of 64 covering causal range
    attn_load_kv(KV, sK, sV, b, g, 0, tid);

    for (int t = 0; t < T; ++t) {
        const int s = t & 1;
        const int kb = t * 64;
        if (t + 1 < T) {
            attn_load_kv(KV, sK + (s ^ 1) * ATT_KF, sV + (s ^ 1) * ATT_VF,
                         b, g, (t + 1) * 64, tid);
            cp_wait<1>();
        } else {
            cp_wait<0>();
        }
        __syncthreads();

        if (kb <= q0 + 15) {                // warp has unmasked work in this tile
            const float* sKc = sK + s * ATT_KF;
            const float* sVc = sV + s * ATT_VF;

            // S = Q K^T  (16 x 64 per warp)
            float sc[8][4];
#pragma unroll
            for (int j = 0; j < 8; ++j)
#pragma unroll
                for (int r = 0; r < 4; ++r) sc[j][r] = 0.f;

#pragma unroll
            for (int ks = 0; ks < 8; ++ks) {
                const float* ap = sQw + ks * 8 + tig;
                uint32_t a[4] = { f2tf32(ap[0]),  f2tf32(ap[8 * QSTR]),
                                  f2tf32(ap[4]),  f2tf32(ap[8 * QSTR + 4]) };
#pragma unroll
                for (int jn = 0; jn < 8; ++jn) {
                    const float* kp = sKc + (jn * 8 + gid) * KSTR + ks * 8 + tig;
                    uint32_t bb[2] = { f2tf32(kp[0]), f2tf32(kp[4]) };
                    mma1688(sc[jn], a, bb);
                }
            }

            // causal mask (only diagonal-region tiles)
            if (kb + 63 > q0) {
                const int r0g = q0 + gid, r1g = r0g + 8;
#pragma unroll
                for (int jn = 0; jn < 8; ++jn) {
                    int col = kb + jn * 8 + 2 * tig;
                    if (col     > r0g) sc[jn][0] = -1e30f;
                    if (col + 1 > r0g) sc[jn][1] = -1e30f;
                    if (col     > r1g) sc[jn][2] = -1e30f;
                    if (col + 1 > r1g) sc[jn][3] = -1e30f;
                }
            }

            // online softmax (base-2 logits)
            float rm0 = -1e30f, rm1 = -1e30f;
#pragma unroll
            for (int jn = 0; jn < 8; ++jn) {
                rm0 = fmaxf(rm0, fmaxf(sc[jn][0], sc[jn][1]));
                rm1 = fmaxf(rm1, fmaxf(sc[jn][2], sc[jn][3]));
            }
            rm0 = fmaxf(rm0, __shfl_xor_sync(0xffffffffu, rm0, 1));
            rm0 = fmaxf(rm0, __shfl_xor_sync(0xffffffffu, rm0, 2));
            rm1 = fmaxf(rm1, __shfl_xor_sync(0xffffffffu, rm1, 1));
            rm1 = fmaxf(rm1, __shfl_xor_sync(0xffffffffu, rm1, 2));

            float mn0 = fmaxf(m0, rm0), mn1 = fmaxf(m1, rm1);
            float c0 = ex2(m0 - mn0), c1 = ex2(m1 - mn1);
            m0 = mn0; m1 = mn1;

            float rs0 = 0.f, rs1 = 0.f;
#pragma unroll
            for (int jn = 0; jn < 8; ++jn) {
                sc[jn][0] = ex2(sc[jn][0] - m0);
                sc[jn][1] = ex2(sc[jn][1] - m0);
                sc[jn][2] = ex2(sc[jn][2] - m1);
                sc[jn][3] = ex2(sc[jn][3] - m1);
                rs0 += sc[jn][0] + sc[jn][1];
                rs1 += sc[jn][2] + sc[jn][3];
            }
            rs0 += __shfl_xor_sync(0xffffffffu, rs0, 1);
            rs0 += __shfl_xor_sync(0xffffffffu, rs0, 2);
            rs1 += __shfl_xor_sync(0xffffffffu, rs1, 1);
            rs1 += __shfl_xor_sync(0xffffffffu, rs1, 2);
            l0 = l0 * c0 + rs0;
            l1 = l1 * c1 + rs1;
#pragma unroll
            for (int jn = 0; jn < 8; ++jn) {
                oa[jn][0] *= c0; oa[jn][1] *= c0;
                oa[jn][2] *= c1; oa[jn][3] *= c1;
            }

            // O += P V  (P-accum -> A-fragments via quad shuffles)
#pragma unroll
            for (int ks = 0; ks < 8; ++ks) {
                const int srcA = (lane & ~3) | (tig >> 1);
                float e0 = __shfl_sync(0xffffffffu, sc[ks][0], srcA);
                float o0 = __shfl_sync(0xffffffffu, sc[ks][1], srcA);
                float e1 = __shfl_sync(0xffffffffu, sc[ks][2], srcA);
                float o1 = __shfl_sync(0xffffffffu, sc[ks][3], srcA);
                float e2 = __shfl_sync(0xffffffffu, sc[ks][0], srcA + 2);
                float o2 = __shfl_sync(0xffffffffu, sc[ks][1], srcA + 2);
                float e3 = __shfl_sync(0xffffffffu, sc[ks][2], srcA + 2);
                float o3 = __shfl_sync(0xffffffffu, sc[ks][3], srcA + 2);
                const bool odd = tig & 1;
                uint32_t a[4];
                a[0] = f2tf32(odd ? o0 : e0);
                a[1] = f2tf32(odd ? o1 : e1);
                a[2] = f2tf32(odd ? o2 : e2);
                a[3] = f2tf32(odd ? o3 : e3);
                const float* vp = sVc + (ks * 8 + tig) * VSTR + gid;
#pragma unroll
                for (int jn = 0; jn < 8; ++jn) {
                    uint32_t bb[2] = { f2tf32(vp[jn * 8]), f2tf32(vp[4 * VSTR + jn * 8]) };
                    mma1688(oa[jn], a, bb);
                }
            }
        }
        __syncthreads();
    }

    // epilogue
    const float i0 = 1.f / l0, i1 = 1.f / l1;
    float* p0 = CTX + (size_t)(b * SEQ + q0 + gid) * DOUT + h * HD;
    float* p1 = CTX + (size_t)(b * SEQ + q0 + gid + 8) * DOUT + h * HD;
#pragma unroll
    for (int jn = 0; jn < 8; ++jn) {
        *(float2*)(p0 + jn * 8 + 2 * tig) = make_float2(oa[jn][0] * i0, oa[jn][1] * i0);
        *(float2*)(p1 + jn * 8 + 2 * tig) = make_float2(oa[jn][2] * i1, oa[jn][3] * i1);
    }
}

// ---------------- kernel_launch ----------------
extern "C" void kernel_launch(void* const* d_in, const int* in_sizes, int n_in,
                              void* d_out, int out_size) {
    const float* x    = (const float*)d_in[0];
    const float* cosT = (const float*)d_in[1];
    const float* sinT = (const float*)d_in[2];
    const float* Wq   = (const float*)d_in[4];
    const float* Wk   = (const float*)d_in[5];
    const float* Wv   = (const float*)d_in[6];
    const float* Wo   = (const float*)d_in[7];
    float* out = (float*)d_out;

    float *Q, *KV, *CTX, *WqT, *WkvT, *WoT;
    cudaGetSymbolAddress((void**)&Q,    g_Q);
    cudaGetSymbolAddress((void**)&KV,   g_KV);
    cudaGetSymbolAddress((void**)&CTX,  g_CTX);
    cudaGetSymbolAddress((void**)&WqT,  g_WqT);
    cudaGetSymbolAddress((void**)&WkvT, g_WkvT);
    cudaGetSymbolAddress((void**)&WoT,  g_WoT);

    cudaFuncSetAttribute(gemm_tf32, cudaFuncAttributeMaxDynamicSharedMemorySize, GEMM_SMEM);
    cudaFuncSetAttribute(attn_tc,   cudaFuncAttributeMaxDynamicSharedMemorySize, ATT_SMEM);

    // transpose weights to K-major [N][2048]
    transpose_k<<<dim3(DOUT / 32, DIN / 32), dim3(32, 8)>>>(Wq, WqT, DIN, DOUT);
    transpose_k<<<dim3(512  / 32, DIN / 32), dim3(32, 8)>>>(Wk, WkvT,                     DIN, 512);
    transpose_k<<<dim3(512  / 32, DIN / 32), dim3(32, 8)>>>(Wv, WkvT + (size_t)512 * DIN, DIN, 512);
    transpose_k<<<dim3(DOUT / 32, DIN / 32), dim3(32, 8)>>>(Wo, WoT, DIN, DOUT);

    // projections (tf32 tensor cores, 2-term A-split compensation)
    gemm_tf32<<<dim3(DOUT / BN, ROWS / BM), 256, GEMM_SMEM>>>(x, WqT,  Q,  DOUT);
    gemm_tf32<<<dim3(DKV  / BN, ROWS / BM), 256, GEMM_SMEM>>>(x, WkvT, KV, DKV);

    // RoPE on Q and on K half of KV
    int totQ = ROWS * NH * 32;
    rope_kernel<<<(totQ + 255) / 256, 256>>>(Q, cosT, sinT, DOUT, NH, totQ);
    int totK = ROWS * NKV * 32;
    rope_kernel<<<(totK + 255) / 256, 256>>>(KV, cosT, sinT, DKV, NKV, totK);

    // tensor-core flash attention
    attn_tc<<<dim3(SEQ / 128, NH, BATCH), 256, ATT_SMEM>>>(Q, KV, CTX);

    // output projection
    gemm_tf32<<<dim3(DOUT / BN, ROWS / BM), 256, GEMM_SMEM>>>(CTX, WoT, out, DOUT);
}

// round 6
// speedup vs baseline: 4.2953x; 1.2490x over previous
#include <cuda_runtime.h>
#include <cuda_bf16.h>
#include <math.h>
#include <stdint.h>

// ---------------- problem constants ----------------
#define BATCH 2
#define SEQ   2048
#define DIN   2048
#define DOUT  2048
#define NH    32
#define HD    64
#define NKV   8
#define ROWS  4096          // BATCH*SEQ
#define DKV   1024          // K(512) | V(512) packed per row

typedef __nv_bfloat16 bf16;

// ---------------- scratch (device globals; no runtime alloc) ----------------
__device__ float g_Q  [(size_t)ROWS * DOUT];
__device__ float g_KV [(size_t)ROWS * DKV];
__device__ bf16  g_Xh [(size_t)ROWS * DIN];
__device__ bf16  g_Xl [(size_t)ROWS * DIN];
__device__ bf16  g_CTXh[(size_t)ROWS * DOUT];
__device__ bf16  g_CTXl[(size_t)ROWS * DOUT];
__device__ bf16  g_WqTh[(size_t)DOUT * DIN];
__device__ bf16  g_WqTl[(size_t)DOUT * DIN];
__device__ bf16  g_WkvTh[(size_t)DKV * DIN];
__device__ bf16  g_WkvTl[(size_t)DKV * DIN];
__device__ bf16  g_WoTh[(size_t)DOUT * DIN];
__device__ bf16  g_WoTl[(size_t)DOUT * DIN];

// ---------------- helpers ----------------
__device__ __forceinline__ uint32_t smem_u32(const void* p) {
    uint32_t a;
    asm("{ .reg .u64 t; cvta.to.shared.u64 t, %1; cvt.u32.u64 %0, t; }" : "=r"(a) : "l"(p));
    return a;
}
__device__ __forceinline__ void cp16(uint32_t dst, const void* src) {
    asm volatile("cp.async.cg.shared.global [%0], [%1], 16;" :: "r"(dst), "l"(src) : "memory");
}
__device__ __forceinline__ void cp_commit() { asm volatile("cp.async.commit_group;" ::: "memory"); }
template<int N> __device__ __forceinline__ void cp_wait() {
    asm volatile("cp.async.wait_group %0;" :: "n"(N) : "memory");
}
__device__ __forceinline__ uint32_t f2tf32(float f) {
    uint32_t u; asm("cvt.rna.tf32.f32 %0, %1;" : "=r"(u) : "f"(f)); return u;
}
__device__ __forceinline__ float ex2(float x) {
    float y; asm("ex2.approx.ftz.f32 %0, %1;" : "=f"(y) : "f"(x)); return y;
}
__device__ __forceinline__ void mma1688(float* d, const uint32_t* a, const uint32_t* b) {
    asm volatile("mma.sync.aligned.m16n8k8.row.col.f32.tf32.tf32.f32 "
        "{%0,%1,%2,%3}, {%4,%5,%6,%7}, {%8,%9}, {%0,%1,%2,%3};"
        : "+f"(d[0]), "+f"(d[1]), "+f"(d[2]), "+f"(d[3])
        : "r"(a[0]), "r"(a[1]), "r"(a[2]), "r"(a[3]), "r"(b[0]), "r"(b[1]));
}
__device__ __forceinline__ void mma16816(float* d, const uint32_t* a, const uint32_t* b) {
    asm volatile("mma.sync.aligned.m16n8k16.row.col.f32.bf16.bf16.f32 "
        "{%0,%1,%2,%3}, {%4,%5,%6,%7}, {%8,%9}, {%0,%1,%2,%3};"
        : "+f"(d[0]), "+f"(d[1]), "+f"(d[2]), "+f"(d[3])
        : "r"(a[0]), "r"(a[1]), "r"(a[2]), "r"(a[3]), "r"(b[0]), "r"(b[1]));
}
__device__ __forceinline__ void ldm_x4(uint32_t* r, uint32_t addr) {
    asm volatile("ldmatrix.sync.aligned.m8n8.x4.shared.b16 {%0,%1,%2,%3}, [%4];"
        : "=r"(r[0]), "=r"(r[1]), "=r"(r[2]), "=r"(r[3]) : "r"(addr));
}
__device__ __forceinline__ void split_bf16(float v, bf16& h, bf16& l) {
    h = __float2bfloat16(v);
    l = __float2bfloat16(v - __bfloat162float(h));
}

// ---------------- split fp32 -> bf16 hi/lo ----------------
__global__ void split_f32(const float* __restrict__ in, bf16* __restrict__ oh,
                          bf16* __restrict__ ol, int n4) {
    int i = blockIdx.x * blockDim.x + threadIdx.x;
    if (i >= n4) return;
    float4 v = ((const float4*)in)[i];
    bf16 h0, h1, h2, h3, l0, l1, l2, l3;
    split_bf16(v.x, h0, l0); split_bf16(v.y, h1, l1);
    split_bf16(v.z, h2, l2); split_bf16(v.w, h3, l3);
    ((__nv_bfloat162*)oh)[2 * i]     = __nv_bfloat162(h0, h1);
    ((__nv_bfloat162*)oh)[2 * i + 1] = __nv_bfloat162(h2, h3);
    ((__nv_bfloat162*)ol)[2 * i]     = __nv_bfloat162(l0, l1);
    ((__nv_bfloat162*)ol)[2 * i + 1] = __nv_bfloat162(l2, l3);
}

// ---------------- transpose + split: in[K][N] fp32 -> outh/outl[N][K] bf16 ----
__global__ void transpose_split(const float* __restrict__ in, bf16* __restrict__ outh,
                                bf16* __restrict__ outl, int K, int N) {
    __shared__ float t[32][33];
    int nb = blockIdx.x * 32, kb = blockIdx.y * 32;
    int tx = threadIdx.x, ty = threadIdx.y; // 32 x 8
#pragma unroll
    for (int i = 0; i < 32; i += 8)
        t[ty + i][tx] = in[(size_t)(kb + ty + i) * N + nb + tx];
    __syncthreads();
#pragma unroll
    for (int i = 0; i < 32; i += 8) {
        float v = t[tx][ty + i];
        bf16 h, l; split_bf16(v, h, l);
        size_t o = (size_t)(nb + ty + i) * K + kb + tx;
        outh[o] = h; outl[o] = l;
    }
}

// ---------------- bf16x3 mma.sync GEMM: C = (Ah+Al)(Bh+Bl)^T -------------
// CTA 128x128, BK=32, 3-stage cp.async, 8 warps (warp tile 64x32).
#define BM 128
#define BN 128
#define BK 32
#define NSTG 3
#define KITER (DIN / BK)                 // 64
#define HS 40                            // halfs per smem row (pad 8 -> 80B stride)
#define GS_TILE (128 * HS)               // halfs per matrix tile
#define GS_STAGE (4 * GS_TILE)           // Ah, Al, Bh, Bl
#define GEMM_SMEM (NSTG * GS_STAGE * 2)  // bytes (122880)

__device__ __forceinline__ void load_stage3(const bf16* __restrict__ Ah,
                                            const bf16* __restrict__ Al,
                                            const bf16* __restrict__ Bh,
                                            const bf16* __restrict__ Bl,
                                            uint32_t st, int m0, int n0, int k0, int tid) {
#pragma unroll
    for (int t = 0; t < 2; ++t) {
        int idx = t * 256 + tid;         // 0..511
        int r = idx >> 2, c = idx & 3;   // 128 rows x 4 chunks (8 halfs)
        uint32_t off = (r * HS + c * 8) * 2;
        size_t ga = (size_t)(m0 + r) * DIN + k0 + c * 8;
        size_t gb = (size_t)(n0 + r) * DIN + k0 + c * 8;
        cp16(st + off,                   Ah + ga);
        cp16(st + GS_TILE * 2 + off,     Al + ga);
        cp16(st + 2 * GS_TILE * 2 + off, Bh + gb);
        cp16(st + 3 * GS_TILE * 2 + off, Bl + gb);
    }
    cp_commit();
}

__global__ __launch_bounds__(256, 1) void gemm_bf16x3(const bf16* __restrict__ Ah,
                                                      const bf16* __restrict__ Al,
                                                      const bf16* __restrict__ Bh,
                                                      const bf16* __restrict__ Bl,
                                                      float* __restrict__ C, int Ntot) {
    extern __shared__ char smem_raw[];
    const uint32_t sbase = smem_u32(smem_raw);
    const int tid  = threadIdx.x;
    const int lane = tid & 31;
    const int warp = tid >> 5;
    const int wm = warp & 1;
    const int wn = warp >> 1;
    const int gid = lane >> 2;
    const int tig = lane & 3;
    const int m0 = blockIdx.y * BM;
    const int n0 = blockIdx.x * BN;

    // per-lane ldmatrix address components
    const int arow = lane & 15;
    const int acol = (lane >> 4) * 8;
    const int brow = (lane & 7) + ((lane >> 4) << 3);
    const int bcol = ((lane >> 3) & 1) * 8;

    float acc[4][4][4];
#pragma unroll
    for (int i = 0; i < 4; ++i)
#pragma unroll
        for (int j = 0; j < 4; ++j)
#pragma unroll
            for (int r = 0; r < 4; ++r) acc[i][j][r] = 0.f;

#pragma unroll
    for (int s = 0; s < NSTG - 1; ++s)
        load_stage3(Ah, Al, Bh, Bl, sbase + s * GS_STAGE * 2, m0, n0, s * BK, tid);
    int load_it = NSTG - 1;

    for (int it = 0; it < KITER; ++it) {
        if (load_it < KITER) {
            load_stage3(Ah, Al, Bh, Bl, sbase + (load_it % NSTG) * GS_STAGE * 2,
                        m0, n0, load_it * BK, tid);
            ++load_it;
        }
        cp_wait<NSTG - 1>();
        __syncthreads();

        const uint32_t st = sbase + (it % NSTG) * GS_STAGE * 2;

#pragma unroll
        for (int k16 = 0; k16 < 2; ++k16) {
            const int kc = k16 * 16;
            uint32_t ah[4][4], al[4][4], bh[4][2], bl[4][2];
#pragma unroll
            for (int mt = 0; mt < 4; ++mt) {
                uint32_t addr = st + ((wm * 64 + mt * 16 + arow) * HS + kc + acol) * 2;
                ldm_x4(ah[mt], addr);
                ldm_x4(al[mt], addr + GS_TILE * 2);
            }
#pragma unroll
            for (int pr = 0; pr < 2; ++pr) {
                uint32_t addr = st + 2 * GS_TILE * 2 +
                                ((wn * 32 + pr * 16 + brow) * HS + kc + bcol) * 2;
                uint32_t t4[4];
                ldm_x4(t4, addr);
                bh[2 * pr][0] = t4[0]; bh[2 * pr][1] = t4[1];
                bh[2 * pr + 1][0] = t4[2]; bh[2 * pr + 1][1] = t4[3];
                ldm_x4(t4, addr + GS_TILE * 2);
                bl[2 * pr][0] = t4[0]; bl[2 * pr][1] = t4[1];
                bl[2 * pr + 1][0] = t4[2]; bl[2 * pr + 1][1] = t4[3];
            }
#pragma unroll
            for (int mt = 0; mt < 4; ++mt)
#pragma unroll
                for (int nt = 0; nt < 4; ++nt) {
                    mma16816(acc[mt][nt], ah[mt], bh[nt]);
                    mma16816(acc[mt][nt], ah[mt], bl[nt]);
                    mma16816(acc[mt][nt], al[mt], bh[nt]);
                }
        }
        __syncthreads();
    }

#pragma unroll
    for (int mt = 0; mt < 4; ++mt) {
        const int row = m0 + wm * 64 + mt * 16 + gid;
#pragma unroll
        for (int nt = 0; nt < 4; ++nt) {
            const int col = n0 + wn * 32 + nt * 8 + 2 * tig;
            *(float2*)(C + (size_t)row * Ntot + col)       = make_float2(acc[mt][nt][0], acc[mt][nt][1]);
            *(float2*)(C + (size_t)(row + 8) * Ntot + col) = make_float2(acc[mt][nt][2], acc[mt][nt][3]);
        }
    }
}

// ---------------- RoPE (in place) ----------------
__global__ void rope_kernel(float* __restrict__ T, const float* __restrict__ cosT,
                            const float* __restrict__ sinT, int rowStride,
                            int nHeads, int total) {
    int idx = blockIdx.x * blockDim.x + threadIdx.x;
    if (idx >= total) return;
    int per_row = nHeads * 32;
    int row = idx / per_row;
    int r = idx - row * per_row;
    int h = r >> 5;
    int d = r & 31;
    int s = row & (SEQ - 1);

    float* p = T + (size_t)row * rowStride + h * 64;
    float x1 = p[d], x2 = p[d + 32];
    float c1 = cosT[s * 64 + d],      s1 = sinT[s * 64 + d];
    float c2 = cosT[s * 64 + d + 32], s2 = sinT[s * 64 + d + 32];
    p[d]      = x1 * c1 - x2 * s1;
    p[d + 32] = x2 * c2 + x1 * s2;
}

// ---------------- tensor-core causal flash attention (tf32 mma.sync) ------
#define QSTR 68
#define KSTR 68
#define VSTR 72
#define ATT_QF   (128 * QSTR)
#define ATT_KF   (64 * KSTR)
#define ATT_VF   (64 * VSTR)
#define ATT_SMEM ((ATT_QF + 2 * ATT_KF + 2 * ATT_VF) * 4)
#define CS 0.1803368801111244f   // 0.125 / ln(2)

__device__ __forceinline__ void attn_load_kv(const float* __restrict__ KV,
                                             float* sK, float* sV,
                                             int b, int g, int kb, int tid) {
    uint32_t k_s = smem_u32(sK), v_s = smem_u32(sV);
#pragma unroll
    for (int t = 0; t < 4; ++t) {
        int idx = t * 256 + tid;
        int r = idx >> 4, c = idx & 15;
        const float* src = KV + (size_t)(b * SEQ + kb + r) * DKV + g * HD + c * 4;
        cp16(k_s + (r * KSTR + c * 4) * 4, src);
        cp16(v_s + (r * VSTR + c * 4) * 4, src + 512);
    }
    cp_commit();
}

__global__ __launch_bounds__(256) void attn_tc(const float* __restrict__ Q,
                                               const float* __restrict__ KV,
                                               bf16* __restrict__ CTXh,
                                               bf16* __restrict__ CTXl) {
    extern __shared__ float sm[];
    float* sQ = sm;
    float* sK = sm + ATT_QF;
    float* sV = sm + ATT_QF + 2 * ATT_KF;

    const int tid = threadIdx.x;
    const int lane = tid & 31;
    const int w = tid >> 5;
    const int gid = lane >> 2;
    const int tig = lane & 3;
    const int qt = (int)gridDim.x - 1 - (int)blockIdx.x;   // big causal ranges first
    const int h = blockIdx.y;
    const int b = blockIdx.z;
    const int g = h >> 2;

    {
        uint32_t q_s = smem_u32(sQ);
#pragma unroll
        for (int t = 0; t < 8; ++t) {
            int idx = t * 256 + tid;
            int r = idx >> 4, c = idx & 15;
            cp16(q_s + (r * QSTR + c * 4) * 4,
                 Q + (size_t)(b * SEQ + qt * 128 + r) * DOUT + h * HD + c * 4);
        }
    }
    cp_commit();
    cp_wait<0>();
    __syncthreads();
    for (int i = tid; i < 128 * 64; i += 256)
        sQ[(i >> 6) * QSTR + (i & 63)] *= CS;
    __syncthreads();

    const int q0 = qt * 128 + w * 16;
    float m0 = -1e30f, m1 = -1e30f, l0 = 0.f, l1 = 0.f;
    float oa[8][4];
#pragma unroll
    for (int j = 0; j < 8; ++j)
#pragma unroll
        for (int r = 0; r < 4; ++r) oa[j][r] = 0.f;

    const float* sQw = sQ + (w * 16 + gid) * QSTR;

    const int T = 2 * qt + 2;
    attn_load_kv(KV, sK, sV, b, g, 0, tid);

    for (int t = 0; t < T; ++t) {
        const int s = t & 1;
        const int kb = t * 64;
        if (t + 1 < T) {
            attn_load_kv(KV, sK + (s ^ 1) * ATT_KF, sV + (s ^ 1) * ATT_VF,
                         b, g, (t + 1) * 64, tid);
            cp_wait<1>();
        } else {
            cp_wait<0>();
        }
        __syncthreads();

        if (kb <= q0 + 15) {
            const float* sKc = sK + s * ATT_KF;
            const float* sVc = sV + s * ATT_VF;

            float sc[8][4];
#pragma unroll
            for (int j = 0; j < 8; ++j)
#pragma unroll
                for (int r = 0; r < 4; ++r) sc[j][r] = 0.f;

#pragma unroll
            for (int ks = 0; ks < 8; ++ks) {
                const float* ap = sQw + ks * 8 + tig;
                uint32_t a[4] = { f2tf32(ap[0]),  f2tf32(ap[8 * QSTR]),
                                  f2tf32(ap[4]),  f2tf32(ap[8 * QSTR + 4]) };
#pragma unroll
                for (int jn = 0; jn < 8; ++jn) {
                    const float* kp = sKc + (jn * 8 + gid) * KSTR + ks * 8 + tig;
                    uint32_t bb[2] = { f2tf32(kp[0]), f2tf32(kp[4]) };
                    mma1688(sc[jn], a, bb);
                }
            }

            if (kb + 63 > q0) {
                const int r0g = q0 + gid, r1g = r0g + 8;
#pragma unroll
                for (int jn = 0; jn < 8; ++jn) {
                    int col = kb + jn * 8 + 2 * tig;
                    if (col     > r0g) sc[jn][0] = -1e30f;
                    if (col + 1 > r0g) sc[jn][1] = -1e30f;
                    if (col     > r1g) sc[jn][2] = -1e30f;
                    if (col + 1 > r1g) sc[jn][3] = -1e30f;
                }
            }

            float rm0 = -1e30f, rm1 = -1e30f;
#pragma unroll
            for (int jn = 0; jn < 8; ++jn) {
                rm0 = fmaxf(rm0, fmaxf(sc[jn][0], sc[jn][1]));
                rm1 = fmaxf(rm1, fmaxf(sc[jn][2], sc[jn][3]));
            }
            rm0 = fmaxf(rm0, __shfl_xor_sync(0xffffffffu, rm0, 1));
            rm0 = fmaxf(rm0, __shfl_xor_sync(0xffffffffu, rm0, 2));
            rm1 = fmaxf(rm1, __shfl_xor_sync(0xffffffffu, rm1, 1));
            rm1 = fmaxf(rm1, __shfl_xor_sync(0xffffffffu, rm1, 2));

            float mn0 = fmaxf(m0, rm0), mn1 = fmaxf(m1, rm1);
            float c0 = ex2(m0 - mn0), c1 = ex2(m1 - mn1);
            m0 = mn0; m1 = mn1;

            float rs0 = 0.f, rs1 = 0.f;
#pragma unroll
            for (int jn = 0; jn < 8; ++jn) {
                sc[jn][0] = ex2(sc[jn][0] - m0);
                sc[jn][1] = ex2(sc[jn][1] - m0);
                sc[jn][2] = ex2(sc[jn][2] - m1);
                sc[jn][3] = ex2(sc[jn][3] - m1);
                rs0 += sc[jn][0] + sc[jn][1];
                rs1 += sc[jn][2] + sc[jn][3];
            }
            rs0 += __shfl_xor_sync(0xffffffffu, rs0, 1);
            rs0 += __shfl_xor_sync(0xffffffffu, rs0, 2);
            rs1 += __shfl_xor_sync(0xffffffffu, rs1, 1);
            rs1 += __shfl_xor_sync(0xffffffffu, rs1, 2);
            l0 = l0 * c0 + rs0;
            l1 = l1 * c1 + rs1;
#pragma unroll
            for (int jn = 0; jn < 8; ++jn) {
                oa[jn][0] *= c0; oa[jn][1] *= c0;
                oa[jn][2] *= c1; oa[jn][3] *= c1;
            }

#pragma unroll
            for (int ks = 0; ks < 8; ++ks) {
                const int srcA = (lane & ~3) | (tig >> 1);
                float e0 = __shfl_sync(0xffffffffu, sc[ks][0], srcA);
                float o0 = __shfl_sync(0xffffffffu, sc[ks][1], srcA);
                float e1 = __shfl_sync(0xffffffffu, sc[ks][2], srcA);
                float o1 = __shfl_sync(0xffffffffu, sc[ks][3], srcA);
                float e2 = __shfl_sync(0xffffffffu, sc[ks][0], srcA + 2);
                float o2 = __shfl_sync(0xffffffffu, sc[ks][1], srcA + 2);
                float e3 = __shfl_sync(0xffffffffu, sc[ks][2], srcA + 2);
                float o3 = __shfl_sync(0xffffffffu, sc[ks][3], srcA + 2);
                const bool odd = tig & 1;
                uint32_t a[4];
                a[0] = f2tf32(odd ? o0 : e0);
                a[1] = f2tf32(odd ? o1 : e1);
                a[2] = f2tf32(odd ? o2 : e2);
                a[3] = f2tf32(odd ? o3 : e3);
                const float* vp = sVc + (ks * 8 + tig) * VSTR + gid;
#pragma unroll
                for (int jn = 0; jn < 8; ++jn) {
                    uint32_t bb[2] = { f2tf32(vp[jn * 8]), f2tf32(vp[4 * VSTR + jn * 8]) };
                    mma1688(oa[jn], a, bb);
                }
            }
        }
        __syncthreads();
    }

    // epilogue: write CTX as bf16 hi/lo
    const float i0 = 1.f / l0, i1 = 1.f / l1;
    const size_t r0 = (size_t)(b * SEQ + q0 + gid) * DOUT + h * HD;
    const size_t r1 = (size_t)(b * SEQ + q0 + gid + 8) * DOUT + h * HD;
#pragma unroll
    for (int jn = 0; jn < 8; ++jn) {
        float v0 = oa[jn][0] * i0, v1 = oa[jn][1] * i0;
        float v2 = oa[jn][2] * i1, v3 = oa[jn][3] * i1;
        bf16 h0, h1, h2, h3, lo0, lo1, lo2, lo3;
        split_bf16(v0, h0, lo0); split_bf16(v1, h1, lo1);
        split_bf16(v2, h2, lo2); split_bf16(v3, h3, lo3);
        size_t o0 = r0 + jn * 8 + 2 * tig;
        size_t o1 = r1 + jn * 8 + 2 * tig;
        *(__nv_bfloat162*)(CTXh + o0) = __nv_bfloat162(h0, h1);
        *(__nv_bfloat162*)(CTXl + o0) = __nv_bfloat162(lo0, lo1);
        *(__nv_bfloat162*)(CTXh + o1) = __nv_bfloat162(h2, h3);
        *(__nv_bfloat162*)(CTXl + o1) = __nv_bfloat162(lo2, lo3);
    }
}

// ---------------- kernel_launch ----------------
extern "C" void kernel_launch(void* const* d_in, const int* in_sizes, int n_in,
                              void* d_out, int out_size) {
    const float* x    = (const float*)d_in[0];
    const float* cosT = (const float*)d_in[1];
    const float* sinT = (const float*)d_in[2];
    const float* Wq   = (const float*)d_in[4];
    const float* Wk   = (const float*)d_in[5];
    const float* Wv   = (const float*)d_in[6];
    const float* Wo   = (const float*)d_in[7];
    float* out = (float*)d_out;

    float *Q, *KV;
    bf16 *Xh, *Xl, *CTXh, *CTXl, *WqTh, *WqTl, *WkvTh, *WkvTl, *WoTh, *WoTl;
    cudaGetSymbolAddress((void**)&Q,     g_Q);
    cudaGetSymbolAddress((void**)&KV,    g_KV);
    cudaGetSymbolAddress((void**)&Xh,    g_Xh);
    cudaGetSymbolAddress((void**)&Xl,    g_Xl);
    cudaGetSymbolAddress((void**)&CTXh,  g_CTXh);
    cudaGetSymbolAddress((void**)&CTXl,  g_CTXl);
    cudaGetSymbolAddress((void**)&WqTh,  g_WqTh);
    cudaGetSymbolAddress((void**)&WqTl,  g_WqTl);
    cudaGetSymbolAddress((void**)&WkvTh, g_WkvTh);
    cudaGetSymbolAddress((void**)&WkvTl, g_WkvTl);
    cudaGetSymbolAddress((void**)&WoTh,  g_WoTh);
    cudaGetSymbolAddress((void**)&WoTl,  g_WoTl);

    cudaFuncSetAttribute(gemm_bf16x3, cudaFuncAttributeMaxDynamicSharedMemorySize, GEMM_SMEM);
    cudaFuncSetAttribute(attn_tc,     cudaFuncAttributeMaxDynamicSharedMemorySize, ATT_SMEM);

    // split x into bf16 hi/lo
    split_f32<<<(ROWS * DIN / 4 + 255) / 256, 256>>>(x, Xh, Xl, ROWS * DIN / 4);

    // transpose + split weights to K-major bf16 hi/lo
    transpose_split<<<dim3(DOUT / 32, DIN / 32), dim3(32, 8)>>>(Wq, WqTh, WqTl, DIN, DOUT);
    transpose_split<<<dim3(512 / 32, DIN / 32), dim3(32, 8)>>>(Wk, WkvTh, WkvTl, DIN, 512);
    transpose_split<<<dim3(512 / 32, DIN / 32), dim3(32, 8)>>>(Wv, WkvTh + (size_t)512 * DIN,
                                                               WkvTl + (size_t)512 * DIN, DIN, 512);
    transpose_split<<<dim3(DOUT / 32, DIN / 32), dim3(32, 8)>>>(Wo, WoTh, WoTl, DIN, DOUT);

    // projections (bf16x3 tensor cores)
    gemm_bf16x3<<<dim3(DOUT / BN, ROWS / BM), 256, GEMM_SMEM>>>(Xh, Xl, WqTh, WqTl, Q, DOUT);
    gemm_bf16x3<<<dim3(DKV  / BN, ROWS / BM), 256, GEMM_SMEM>>>(Xh, Xl, WkvTh, WkvTl, KV, DKV);

    // RoPE on Q and on K half of KV
    int totQ = ROWS * NH * 32;
    rope_kernel<<<(totQ + 255) / 256, 256>>>(Q, cosT, sinT, DOUT, NH, totQ);
    int totK = ROWS * NKV * 32;
    rope_kernel<<<(totK + 255) / 256, 256>>>(KV, cosT, sinT, DKV, NKV, totK);

    // tensor-core flash attention (emits CTX hi/lo bf16)
    attn_tc<<<dim3(SEQ / 128, NH, BATCH), 256, ATT_SMEM>>>(Q, KV, CTXh, CTXl);

    // output projection
    gemm_bf16x3<<<dim3(DOUT / BN, ROWS / BM), 256, GEMM_SMEM>>>(CTXh, CTXl, WoTh, WoTl, out, DOUT);
}

// round 7
// speedup vs baseline: 4.6642x; 1.0859x over previous
#include <cuda_runtime.h>
#include <cuda_bf16.h>
#include <math.h>
#include <stdint.h>

// ---------------- problem constants ----------------
#define BATCH 2
#define SEQ   2048
#define DIN   2048
#define DOUT  2048
#define NH    32
#define HD    64
#define NKV   8
#define ROWS  4096          // BATCH*SEQ
#define NQKV  3072          // Q(2048) | K(512) | V(512) per row

typedef __nv_bfloat16 bf16;

// ---------------- scratch (device globals; no runtime alloc) ----------------
__device__ float g_QKV[(size_t)ROWS * NQKV];     // 50 MB
__device__ bf16  g_Xh [(size_t)ROWS * DIN];
__device__ bf16  g_Xl [(size_t)ROWS * DIN];
__device__ bf16  g_CTXh[(size_t)ROWS * DOUT];
__device__ bf16  g_CTXl[(size_t)ROWS * DOUT];
__device__ bf16  g_WTh[(size_t)NQKV * DIN];      // rows: Wq^T | Wk^T | Wv^T
__device__ bf16  g_WTl[(size_t)NQKV * DIN];
__device__ bf16  g_WoTh[(size_t)DOUT * DIN];
__device__ bf16  g_WoTl[(size_t)DOUT * DIN];

// ---------------- helpers ----------------
__device__ __forceinline__ uint32_t smem_u32(const void* p) {
    uint32_t a;
    asm("{ .reg .u64 t; cvta.to.shared.u64 t, %1; cvt.u32.u64 %0, t; }" : "=r"(a) : "l"(p));
    return a;
}
__device__ __forceinline__ void cp16(uint32_t dst, const void* src) {
    asm volatile("cp.async.cg.shared.global [%0], [%1], 16;" :: "r"(dst), "l"(src) : "memory");
}
__device__ __forceinline__ void cp_commit() { asm volatile("cp.async.commit_group;" ::: "memory"); }
template<int N> __device__ __forceinline__ void cp_wait() {
    asm volatile("cp.async.wait_group %0;" :: "n"(N) : "memory");
}
__device__ __forceinline__ uint32_t f2tf32(float f) {
    uint32_t u; asm("cvt.rna.tf32.f32 %0, %1;" : "=r"(u) : "f"(f)); return u;
}
__device__ __forceinline__ float ex2(float x) {
    float y; asm("ex2.approx.ftz.f32 %0, %1;" : "=f"(y) : "f"(x)); return y;
}
__device__ __forceinline__ void mma1688(float* d, const uint32_t* a, const uint32_t* b) {
    asm volatile("mma.sync.aligned.m16n8k8.row.col.f32.tf32.tf32.f32 "
        "{%0,%1,%2,%3}, {%4,%5,%6,%7}, {%8,%9}, {%0,%1,%2,%3};"
        : "+f"(d[0]), "+f"(d[1]), "+f"(d[2]), "+f"(d[3])
        : "r"(a[0]), "r"(a[1]), "r"(a[2]), "r"(a[3]), "r"(b[0]), "r"(b[1]));
}
__device__ __forceinline__ void mma16816(float* d, const uint32_t* a, const uint32_t* b) {
    asm volatile("mma.sync.aligned.m16n8k16.row.col.f32.bf16.bf16.f32 "
        "{%0,%1,%2,%3}, {%4,%5,%6,%7}, {%8,%9}, {%0,%1,%2,%3};"
        : "+f"(d[0]), "+f"(d[1]), "+f"(d[2]), "+f"(d[3])
        : "r"(a[0]), "r"(a[1]), "r"(a[2]), "r"(a[3]), "r"(b[0]), "r"(b[1]));
}
__device__ __forceinline__ void ldm_x4(uint32_t* r, uint32_t addr) {
    asm volatile("ldmatrix.sync.aligned.m8n8.x4.shared.b16 {%0,%1,%2,%3}, [%4];"
        : "=r"(r[0]), "=r"(r[1]), "=r"(r[2]), "=r"(r[3]) : "r"(addr));
}
__device__ __forceinline__ void split_bf16(float v, bf16& h, bf16& l) {
    h = __float2bfloat16(v);
    l = __float2bfloat16(v - __bfloat162float(h));
}

// ---------------- split fp32 -> bf16 hi/lo ----------------
__global__ void split_f32(const float* __restrict__ in, bf16* __restrict__ oh,
                          bf16* __restrict__ ol, int n4) {
    int i = blockIdx.x * blockDim.x + threadIdx.x;
    if (i >= n4) return;
    float4 v = ((const float4*)in)[i];
    bf16 h0, h1, h2, h3, l0, l1, l2, l3;
    split_bf16(v.x, h0, l0); split_bf16(v.y, h1, l1);
    split_bf16(v.z, h2, l2); split_bf16(v.w, h3, l3);
    ((__nv_bfloat162*)oh)[2 * i]     = __nv_bfloat162(h0, h1);
    ((__nv_bfloat162*)oh)[2 * i + 1] = __nv_bfloat162(h2, h3);
    ((__nv_bfloat162*)ol)[2 * i]     = __nv_bfloat162(l0, l1);
    ((__nv_bfloat162*)ol)[2 * i + 1] = __nv_bfloat162(l2, l3);
}

// ---------------- transpose + split: in[K][N] fp32 -> outh/outl[N][K] bf16 ----
__global__ void transpose_split(const float* __restrict__ in, bf16* __restrict__ outh,
                                bf16* __restrict__ outl, int K, int N) {
    __shared__ float t[32][33];
    int nb = blockIdx.x * 32, kb = blockIdx.y * 32;
    int tx = threadIdx.x, ty = threadIdx.y; // 32 x 8
#pragma unroll
    for (int i = 0; i < 32; i += 8)
        t[ty + i][tx] = in[(size_t)(kb + ty + i) * N + nb + tx];
    __syncthreads();
#pragma unroll
    for (int i = 0; i < 32; i += 8) {
        float v = t[tx][ty + i];
        bf16 h, l; split_bf16(v, h, l);
        size_t o = (size_t)(nb + ty + i) * K + kb + tx;
        outh[o] = h; outl[o] = l;
    }
}

// ---------------- bf16x3 mma.sync GEMM: C = (Ah+Al)(Bh+Bl)^T -------------
// CTA 128x128, BK=32, 2-stage cp.async, 8 warps (warp tile 64x32), 2 CTAs/SM.
#define BM 128
#define BN 128
#define BK 32
#define NSTG 2
#define KITER (DIN / BK)                 // 64
#define HS 40                            // halfs per smem row (80B stride)
#define GS_TILE (128 * HS)               // halfs per matrix tile
#define GS_STAGE (4 * GS_TILE)           // Ah, Al, Bh, Bl
#define GEMM_SMEM (NSTG * GS_STAGE * 2)  // 81920 bytes

__device__ __forceinline__ void load_stage3(const bf16* __restrict__ Ah,
                                            const bf16* __restrict__ Al,
                                            const bf16* __restrict__ Bh,
                                            const bf16* __restrict__ Bl,
                                            uint32_t st, int m0, int n0, int k0, int tid) {
#pragma unroll
    for (int t = 0; t < 2; ++t) {
        int idx = t * 256 + tid;         // 0..511
        int r = idx >> 2, c = idx & 3;   // 128 rows x 4 chunks (8 halfs)
        uint32_t off = (r * HS + c * 8) * 2;
        size_t ga = (size_t)(m0 + r) * DIN + k0 + c * 8;
        size_t gb = (size_t)(n0 + r) * DIN + k0 + c * 8;
        cp16(st + off,                   Ah + ga);
        cp16(st + GS_TILE * 2 + off,     Al + ga);
        cp16(st + 2 * GS_TILE * 2 + off, Bh + gb);
        cp16(st + 3 * GS_TILE * 2 + off, Bl + gb);
    }
    cp_commit();
}

__global__ __launch_bounds__(256, 2) void gemm_bf16x3(const bf16* __restrict__ Ah,
                                                      const bf16* __restrict__ Al,
                                                      const bf16* __restrict__ Bh,
                                                      const bf16* __restrict__ Bl,
                                                      float* __restrict__ C, int Ntot) {
    extern __shared__ char smem_raw[];
    const uint32_t sbase = smem_u32(smem_raw);
    const int tid  = threadIdx.x;
    const int lane = tid & 31;
    const int warp = tid >> 5;
    const int wm = warp & 1;
    const int wn = warp >> 1;
    const int gid = lane >> 2;
    const int tig = lane & 3;
    const int m0 = blockIdx.y * BM;
    const int n0 = blockIdx.x * BN;

    const int arow = lane & 15;
    const int acol = (lane >> 4) * 8;
    const int brow = (lane & 7) + ((lane >> 4) << 3);
    const int bcol = ((lane >> 3) & 1) * 8;

    float acc[4][4][4];
#pragma unroll
    for (int i = 0; i < 4; ++i)
#pragma unroll
        for (int j = 0; j < 4; ++j)
#pragma unroll
            for (int r = 0; r < 4; ++r) acc[i][j][r] = 0.f;

    load_stage3(Ah, Al, Bh, Bl, sbase, m0, n0, 0, tid);   // stage 0
    int load_it = 1;

    for (int it = 0; it < KITER; ++it) {
        bool issued = (load_it < KITER);
        if (issued) {
            load_stage3(Ah, Al, Bh, Bl, sbase + (load_it & 1) * GS_STAGE * 2,
                        m0, n0, load_it * BK, tid);
            ++load_it;
        }
        if (issued) cp_wait<NSTG - 1>(); else cp_wait<0>();
        __syncthreads();

        const uint32_t st = sbase + (it & 1) * GS_STAGE * 2;

#pragma unroll
        for (int k16 = 0; k16 < 2; ++k16) {
            const int kc = k16 * 16;
            uint32_t ah[4][4], al[4][4], bh[4][2], bl[4][2];
#pragma unroll
            for (int mt = 0; mt < 4; ++mt) {
                uint32_t addr = st + ((wm * 64 + mt * 16 + arow) * HS + kc + acol) * 2;
                ldm_x4(ah[mt], addr);
                ldm_x4(al[mt], addr + GS_TILE * 2);
            }
#pragma unroll
            for (int pr = 0; pr < 2; ++pr) {
                uint32_t addr = st + 2 * GS_TILE * 2 +
                                ((wn * 32 + pr * 16 + brow) * HS + kc + bcol) * 2;
                uint32_t t4[4];
                ldm_x4(t4, addr);
                bh[2 * pr][0] = t4[0]; bh[2 * pr][1] = t4[1];
                bh[2 * pr + 1][0] = t4[2]; bh[2 * pr + 1][1] = t4[3];
                ldm_x4(t4, addr + GS_TILE * 2);
                bl[2 * pr][0] = t4[0]; bl[2 * pr][1] = t4[1];
                bl[2 * pr + 1][0] = t4[2]; bl[2 * pr + 1][1] = t4[3];
            }
#pragma unroll
            for (int mt = 0; mt < 4; ++mt)
#pragma unroll
                for (int nt = 0; nt < 4; ++nt) {
                    mma16816(acc[mt][nt], ah[mt], bh[nt]);
                    mma16816(acc[mt][nt], ah[mt], bl[nt]);
                    mma16816(acc[mt][nt], al[mt], bh[nt]);
                }
        }
        __syncthreads();
    }

#pragma unroll
    for (int mt = 0; mt < 4; ++mt) {
        const int row = m0 + wm * 64 + mt * 16 + gid;
#pragma unroll
        for (int nt = 0; nt < 4; ++nt) {
            const int col = n0 + wn * 32 + nt * 8 + 2 * tig;
            *(float2*)(C + (size_t)row * Ntot + col)       = make_float2(acc[mt][nt][0], acc[mt][nt][1]);
            *(float2*)(C + (size_t)(row + 8) * Ntot + col) = make_float2(acc[mt][nt][2], acc[mt][nt][3]);
        }
    }
}

// ---------------- RoPE (in place) ----------------
__global__ void rope_kernel(float* __restrict__ T, const float* __restrict__ cosT,
                            const float* __restrict__ sinT, int rowStride,
                            int nHeads, int total) {
    int idx = blockIdx.x * blockDim.x + threadIdx.x;
    if (idx >= total) return;
    int per_row = nHeads * 32;
    int row = idx / per_row;
    int r = idx - row * per_row;
    int h = r >> 5;
    int d = r & 31;
    int s = row & (SEQ - 1);

    float* p = T + (size_t)row * rowStride + h * 64;
    float x1 = p[d], x2 = p[d + 32];
    float c1 = cosT[s * 64 + d],      s1 = sinT[s * 64 + d];
    float c2 = cosT[s * 64 + d + 32], s2 = sinT[s * 64 + d + 32];
    p[d]      = x1 * c1 - x2 * s1;
    p[d + 32] = x2 * c2 + x1 * s2;
}

// ---------------- tensor-core causal flash attention (tf32 mma.sync) ------
#define QSTR 68
#define KSTR 68
#define VSTR 72
#define ATT_QF   (128 * QSTR)
#define ATT_KF   (64 * KSTR)
#define ATT_VF   (64 * VSTR)
#define ATT_SMEM ((ATT_QF + 2 * ATT_KF + 2 * ATT_VF) * 4)
#define CS 0.1803368801111244f   // 0.125 / ln(2)

__device__ __forceinline__ void attn_load_kv(const float* __restrict__ KVbase,
                                             float* sK, float* sV,
                                             int b, int g, int kb, int tid) {
    uint32_t k_s = smem_u32(sK), v_s = smem_u32(sV);
#pragma unroll
    for (int t = 0; t < 4; ++t) {
        int idx = t * 256 + tid;
        int r = idx >> 4, c = idx & 15;
        const float* src = KVbase + (size_t)(b * SEQ + kb + r) * NQKV + g * HD + c * 4;
        cp16(k_s + (r * KSTR + c * 4) * 4, src);
        cp16(v_s + (r * VSTR + c * 4) * 4, src + 512);
    }
    cp_commit();
}

__global__ __launch_bounds__(256) void attn_tc(const float* __restrict__ QKV,
                                               bf16* __restrict__ CTXh,
                                               bf16* __restrict__ CTXl) {
    extern __shared__ float sm[];
    float* sQ = sm;
    float* sK = sm + ATT_QF;
    float* sV = sm + ATT_QF + 2 * ATT_KF;

    const int tid = threadIdx.x;
    const int lane = tid & 31;
    const int w = tid >> 5;
    const int gid = lane >> 2;
    const int tig = lane & 3;
    const int qt = (int)gridDim.x - 1 - (int)blockIdx.x;   // big causal ranges first
    const int h = blockIdx.y;
    const int b = blockIdx.z;
    const int g = h >> 2;
    const float* KVbase = QKV + 2048;   // K at col 2048, V at col 2560

    {
        uint32_t q_s = smem_u32(sQ);
#pragma unroll
        for (int t = 0; t < 8; ++t) {
            int idx = t * 256 + tid;
            int r = idx >> 4, c = idx & 15;
            cp16(q_s + (r * QSTR + c * 4) * 4,
                 QKV + (size_t)(b * SEQ + qt * 128 + r) * NQKV + h * HD + c * 4);
        }
    }
    cp_commit();
    cp_wait<0>();
    __syncthreads();
    for (int i = tid; i < 128 * 64; i += 256)
        sQ[(i >> 6) * QSTR + (i & 63)] *= CS;
    __syncthreads();

    const int q0 = qt * 128 + w * 16;
    float m0 = -1e30f, m1 = -1e30f, l0 = 0.f, l1 = 0.f;
    float oa[8][4];
#pragma unroll
    for (int j = 0; j < 8; ++j)
#pragma unroll
        for (int r = 0; r < 4; ++r) oa[j][r] = 0.f;

    const float* sQw = sQ + (w * 16 + gid) * QSTR;

    const int T = 2 * qt + 2;
    attn_load_kv(KVbase, sK, sV, b, g, 0, tid);

    for (int t = 0; t < T; ++t) {
        const int s = t & 1;
        const int kb = t * 64;
        if (t + 1 < T) {
            attn_load_kv(KVbase, sK + (s ^ 1) * ATT_KF, sV + (s ^ 1) * ATT_VF,
                         b, g, (t + 1) * 64, tid);
            cp_wait<1>();
        } else {
            cp_wait<0>();
        }
        __syncthreads();

        if (kb <= q0 + 15) {
            const float* sKc = sK + s * ATT_KF;
            const float* sVc = sV + s * ATT_VF;

            float sc[8][4];
#pragma unroll
            for (int j = 0; j < 8; ++j)
#pragma unroll
                for (int r = 0; r < 4; ++r) sc[j][r] = 0.f;

#pragma unroll
            for (int ks = 0; ks < 8; ++ks) {
                const float* ap = sQw + ks * 8 + tig;
                uint32_t a[4] = { f2tf32(ap[0]),  f2tf32(ap[8 * QSTR]),
                                  f2tf32(ap[4]),  f2tf32(ap[8 * QSTR + 4]) };
#pragma unroll
                for (int jn = 0; jn < 8; ++jn) {
                    const float* kp = sKc + (jn * 8 + gid) * KSTR + ks * 8 + tig;
                    uint32_t bb[2] = { f2tf32(kp[0]), f2tf32(kp[4]) };
                    mma1688(sc[jn], a, bb);
                }
            }

            if (kb + 63 > q0) {
                const int r0g = q0 + gid, r1g = r0g + 8;
#pragma unroll
                for (int jn = 0; jn < 8; ++jn) {
                    int col = kb + jn * 8 + 2 * tig;
                    if (col     > r0g) sc[jn][0] = -1e30f;
                    if (col + 1 > r0g) sc[jn][1] = -1e30f;
                    if (col     > r1g) sc[jn][2] = -1e30f;
                    if (col + 1 > r1g) sc[jn][3] = -1e30f;
                }
            }

            float rm0 = -1e30f, rm1 = -1e30f;
#pragma unroll
            for (int jn = 0; jn < 8; ++jn) {
                rm0 = fmaxf(rm0, fmaxf(sc[jn][0], sc[jn][1]));
                rm1 = fmaxf(rm1, fmaxf(sc[jn][2], sc[jn][3]));
            }
            rm0 = fmaxf(rm0, __shfl_xor_sync(0xffffffffu, rm0, 1));
            rm0 = fmaxf(rm0, __shfl_xor_sync(0xffffffffu, rm0, 2));
            rm1 = fmaxf(rm1, __shfl_xor_sync(0xffffffffu, rm1, 1));
            rm1 = fmaxf(rm1, __shfl_xor_sync(0xffffffffu, rm1, 2));

            float mn0 = fmaxf(m0, rm0), mn1 = fmaxf(m1, rm1);
            float c0 = ex2(m0 - mn0), c1 = ex2(m1 - mn1);
            m0 = mn0; m1 = mn1;

            float rs0 = 0.f, rs1 = 0.f;
#pragma unroll
            for (int jn = 0; jn < 8; ++jn) {
                sc[jn][0] = ex2(sc[jn][0] - m0);
                sc[jn][1] = ex2(sc[jn][1] - m0);
                sc[jn][2] = ex2(sc[jn][2] - m1);
                sc[jn][3] = ex2(sc[jn][3] - m1);
                rs0 += sc[jn][0] + sc[jn][1];
                rs1 += sc[jn][2] + sc[jn][3];
            }
            rs0 += __shfl_xor_sync(0xffffffffu, rs0, 1);
            rs0 += __shfl_xor_sync(0xffffffffu, rs0, 2);
            rs1 += __shfl_xor_sync(0xffffffffu, rs1, 1);
            rs1 += __shfl_xor_sync(0xffffffffu, rs1, 2);
            l0 = l0 * c0 + rs0;
            l1 = l1 * c1 + rs1;
#pragma unroll
            for (int jn = 0; jn < 8; ++jn) {
                oa[jn][0] *= c0; oa[jn][1] *= c0;
                oa[jn][2] *= c1; oa[jn][3] *= c1;
            }

#pragma unroll
            for (int ks = 0; ks < 8; ++ks) {
                const int srcA = (lane & ~3) | (tig >> 1);
                float e0 = __shfl_sync(0xffffffffu, sc[ks][0], srcA);
                float o0 = __shfl_sync(0xffffffffu, sc[ks][1], srcA);
                float e1 = __shfl_sync(0xffffffffu, sc[ks][2], srcA);
                float o1 = __shfl_sync(0xffffffffu, sc[ks][3], srcA);
                float e2 = __shfl_sync(0xffffffffu, sc[ks][0], srcA + 2);
                float o2 = __shfl_sync(0xffffffffu, sc[ks][1], srcA + 2);
                float e3 = __shfl_sync(0xffffffffu, sc[ks][2], srcA + 2);
                float o3 = __shfl_sync(0xffffffffu, sc[ks][3], srcA + 2);
                const bool odd = tig & 1;
                uint32_t a[4];
                a[0] = f2tf32(odd ? o0 : e0);
                a[1] = f2tf32(odd ? o1 : e1);
                a[2] = f2tf32(odd ? o2 : e2);
                a[3] = f2tf32(odd ? o3 : e3);
                const float* vp = sVc + (ks * 8 + tig) * VSTR + gid;
#pragma unroll
                for (int jn = 0; jn < 8; ++jn) {
                    uint32_t bb[2] = { f2tf32(vp[jn * 8]), f2tf32(vp[4 * VSTR + jn * 8]) };
                    mma1688(oa[jn], a, bb);
                }
            }
        }
        __syncthreads();
    }

    // epilogue: write CTX as bf16 hi/lo
    const float i0 = 1.f / l0, i1 = 1.f / l1;
    const size_t r0 = (size_t)(b * SEQ + q0 + gid) * DOUT + h * HD;
    const size_t r1 = (size_t)(b * SEQ + q0 + gid + 8) * DOUT + h * HD;
#pragma unroll
    for (int jn = 0; jn < 8; ++jn) {
        float v0 = oa[jn][0] * i0, v1 = oa[jn][1] * i0;
        float v2 = oa[jn][2] * i1, v3 = oa[jn][3] * i1;
        bf16 h0, h1, h2, h3, lo0, lo1, lo2, lo3;
        split_bf16(v0, h0, lo0); split_bf16(v1, h1, lo1);
        split_bf16(v2, h2, lo2); split_bf16(v3, h3, lo3);
        size_t o0 = r0 + jn * 8 + 2 * tig;
        size_t o1 = r1 + jn * 8 + 2 * tig;
        *(__nv_bfloat162*)(CTXh + o0) = __nv_bfloat162(h0, h1);
        *(__nv_bfloat162*)(CTXl + o0) = __nv_bfloat162(lo0, lo1);
        *(__nv_bfloat162*)(CTXh + o1) = __nv_bfloat162(h2, h3);
        *(__nv_bfloat162*)(CTXl + o1) = __nv_bfloat162(lo2, lo3);
    }
}

// ---------------- kernel_launch ----------------
extern "C" void kernel_launch(void* const* d_in, const int* in_sizes, int n_in,
                              void* d_out, int out_size) {
    const float* x    = (const float*)d_in[0];
    const float* cosT = (const float*)d_in[1];
    const float* sinT = (const float*)d_in[2];
    const float* Wq   = (const float*)d_in[4];
    const float* Wk   = (const float*)d_in[5];
    const float* Wv   = (const float*)d_in[6];
    const float* Wo   = (const float*)d_in[7];
    float* out = (float*)d_out;

    float *QKV;
    bf16 *Xh, *Xl, *CTXh, *CTXl, *WTh, *WTl, *WoTh, *WoTl;
    cudaGetSymbolAddress((void**)&QKV,   g_QKV);
    cudaGetSymbolAddress((void**)&Xh,    g_Xh);
    cudaGetSymbolAddress((void**)&Xl,    g_Xl);
    cudaGetSymbolAddress((void**)&CTXh,  g_CTXh);
    cudaGetSymbolAddress((void**)&CTXl,  g_CTXl);
    cudaGetSymbolAddress((void**)&WTh,   g_WTh);
    cudaGetSymbolAddress((void**)&WTl,   g_WTl);
    cudaGetSymbolAddress((void**)&WoTh,  g_WoTh);
    cudaGetSymbolAddress((void**)&WoTl,  g_WoTl);

    cudaFuncSetAttribute(gemm_bf16x3, cudaFuncAttributeMaxDynamicSharedMemorySize, GEMM_SMEM);
    cudaFuncSetAttribute(attn_tc,     cudaFuncAttributeMaxDynamicSharedMemorySize, ATT_SMEM);

    // split x into bf16 hi/lo
    split_f32<<<(ROWS * DIN / 4 + 255) / 256, 256>>>(x, Xh, Xl, ROWS * DIN / 4);

    // transpose + split weights into combined K-major [3072][2048]
    transpose_split<<<dim3(DOUT / 32, DIN / 32), dim3(32, 8)>>>(Wq, WTh, WTl, DIN, DOUT);
    transpose_split<<<dim3(512 / 32, DIN / 32), dim3(32, 8)>>>(Wk, WTh + (size_t)2048 * DIN,
                                                               WTl + (size_t)2048 * DIN, DIN, 512);
    transpose_split<<<dim3(512 / 32, DIN / 32), dim3(32, 8)>>>(Wv, WTh + (size_t)2560 * DIN,
                                                               WTl + (size_t)2560 * DIN, DIN, 512);
    transpose_split<<<dim3(DOUT / 32, DIN / 32), dim3(32, 8)>>>(Wo, WoTh, WoTl, DIN, DOUT);

    // fused QKV projection (bf16x3 tensor cores), N = 3072
    gemm_bf16x3<<<dim3(NQKV / BN, ROWS / BM), 256, GEMM_SMEM>>>(Xh, Xl, WTh, WTl, QKV, NQKV);

    // RoPE on Q (cols 0-2047) and K (cols 2048-2559)
    int totQ = ROWS * NH * 32;
    rope_kernel<<<(totQ + 255) / 256, 256>>>(QKV, cosT, sinT, NQKV, NH, totQ);
    int totK = ROWS * NKV * 32;
    rope_kernel<<<(totK + 255) / 256, 256>>>(QKV + 2048, cosT, sinT, NQKV, NKV, totK);

    // tensor-core flash attention (emits CTX hi/lo bf16)
    attn_tc<<<dim3(SEQ / 128, NH, BATCH), 256, ATT_SMEM>>>(QKV, CTXh, CTXl);

    // output projection
    gemm_bf16x3<<<dim3(DOUT / BN, ROWS / BM), 256, GEMM_SMEM>>>(CTXh, CTXl, WoTh, WoTl, out, DOUT);
}